// round 9
// baseline (speedup 1.0000x reference)
#include <cuda_runtime.h>
#include <cuda_bf16.h>
#include <stdint.h>

#define NPTS 200000
#define DIM 64
#define KC 256
#define BW2 144.0f
#define ITERS 10

#define KB 128
#define PB 128
#define FKB 64
#define NT128 1563
#define GXI 74
#define GXF 148
#define XTS 132
#define XRS 68
#define MSS 132
#define NT64 3125
#define SPB 148

typedef unsigned long long u64p;
#define PK2(d, lo, hi) asm("mov.b64 %0, {%1, %2};" : "=l"(d) : "f"(lo), "f"(hi))
#define UPK2(lo, hi, s) asm("mov.b64 {%0, %1}, %2;" : "=f"(lo), "=f"(hi) : "l"(s))
#define FMA2(d, a, b, c) asm("fma.rn.f32x2 %0, %1, %2, %3;" : "=l"(d) : "l"(a), "l"(b), "l"(c))
#define ADD2(d, a, b) asm("add.rn.f32x2 %0, %1, %2;" : "=l"(d) : "l"(a), "l"(b))

__device__ float g_c[2][KC][DIM];
__device__ float g_acc[KC][DIM];          // iter0 exception sums
__device__ float g_cnt[KC];               // iter0 exception counts
__device__ float g_acc2[ITERS - 1][KC][DIM];  // per-sparse-iteration buffers
__device__ float g_cnt2[ITERS - 1][KC];
__device__ double g_sumx[DIM];
__device__ float g_x2[NPTS];
__device__ unsigned long long g_best[KC];
__device__ int g_seed64;
__device__ int g_tileflag[NT64];
__device__ unsigned g_barcnt;
__device__ volatile unsigned g_bargen;

// ------------------------------------------------- prologue kernels

__global__ void detect_kernel(const void* __restrict__ seed) {
    __shared__ int bad;
    if (threadIdx.x == 0) bad = 0;
    if (threadIdx.x < DIM) g_sumx[threadIdx.x] = 0.0;
    __syncthreads();
    unsigned long long v = ((const unsigned long long*)seed)[threadIdx.x];
    if (v >= (unsigned long long)NPTS) atomicOr(&bad, 1);
    __syncthreads();
    if (threadIdx.x == 0) g_seed64 = bad ? 0 : 1;
}

// x2 per point + fused column sum + zeroing of sparse buffers
__global__ void x2_kernel(const float* __restrict__ x) {
    __shared__ float wsum[8][DIM];
    const int tid = threadIdx.x;
    const int n = blockIdx.x * 256 + tid;
    const int lane = tid & 31, wid = tid >> 5;
    const bool valid = n < NPTS;
    const float4* r = (const float4*)(x + (size_t)n * DIM);

    float x2 = 0.f;
#pragma unroll
    for (int q = 0; q < 16; q++) {
        float4 v = valid ? r[q] : make_float4(0.f, 0.f, 0.f, 0.f);
        x2 = fmaf(v.x, v.x, x2); x2 = fmaf(v.y, v.y, x2);
        x2 = fmaf(v.z, v.z, x2); x2 = fmaf(v.w, v.w, x2);
#pragma unroll
        for (int off = 16; off > 0; off >>= 1) {
            v.x += __shfl_xor_sync(0xffffffffu, v.x, off);
            v.y += __shfl_xor_sync(0xffffffffu, v.y, off);
            v.z += __shfl_xor_sync(0xffffffffu, v.z, off);
            v.w += __shfl_xor_sync(0xffffffffu, v.w, off);
        }
        if (lane == 0) *(float4*)&wsum[wid][4 * q] = v;
    }
    if (valid) g_x2[n] = x2;
    if (n < NT64) g_tileflag[n] = 0;
    if (n < (ITERS - 1) * KC * DIM) ((float*)g_acc2)[n] = 0.f;
    if (n < (ITERS - 1) * KC) ((float*)g_cnt2)[n] = 0.f;
    __syncthreads();
    if (tid < DIM) {
        float tot = 0.f;
#pragma unroll
        for (int w = 0; w < 8; w++) tot += wsum[w][tid];
        atomicAdd(&g_sumx[tid], (double)tot);
    }
}

__global__ void seed_kernel(const float* __restrict__ x, const void* __restrict__ seedraw) {
    int k = blockIdx.x, d = threadIdx.x;
    long long idx;
    if (g_seed64) idx = ((const long long*)seedraw)[k];
    else          idx = (long long)(((const int*)seedraw)[k]);
    g_c[0][k][d] = x[idx * DIM + d];
    g_acc[k][d] = 0.f;
    if (d == 0) { g_cnt[k] = 0.f; g_best[k] = ~0ull; }
}

__global__ void update_kernel(int it) {
    int k = blockIdx.x, d = threadIdx.x;
    double cnt = (double)NPTS - (double)g_cnt[k];
    double v = (g_sumx[d] - (double)g_acc[k][d]) / cnt;
    __syncthreads();
    g_c[(it + 1) & 1][k][d] = (float)v;
}

// ------------------------------------------- dense iteration (it=0)
// Round-3 staging restored: Xr and Xt filled from ONE global read per tile.

__global__ void __launch_bounds__(256, 1) iter_kernel(const float* __restrict__ x, int it) {
    extern __shared__ float smem[];
    float* Cs  = smem;
    float* c2s = Cs + 64 * KB;
    float* Xt  = c2s + KB;
    float* Xr  = Xt + 64 * XTS;
    float* Ms  = Xr + PB * XRS;
    float* x2s = Ms + PB * MSS;
    int* flagp = (int*)(x2s + PB);

    const int tid = threadIdx.x;
    const int ty = tid >> 4, tx = tid & 15;
    const int ck0 = ty * 8, p0 = tx * 8, dq = tx * 4;
    const int kb = blockIdx.y * KB;
    const float* cin = &g_c[it & 1][0][0];

    for (int e = tid; e < KB * DIM; e += 256) {
        int ck = e & (KB - 1), d = e >> 7;
        Cs[d * KB + ck] = cin[(size_t)(kb + ck) * DIM + d];
    }
    __syncthreads();
    if (tid < KB) {
        float s = 0.f;
#pragma unroll
        for (int d = 0; d < DIM; d++) { float c = Cs[d * KB + tid]; s = fmaf(c, c, s); }
        c2s[tid] = s;
    }
    __syncthreads();

    u64p c2d[8];
#pragma unroll
    for (int i = 0; i < 8; i++) { float v = c2s[ck0 + i]; PK2(c2d[i], v, v); }
    u64p neg2; { float m2 = -2.0f; PK2(neg2, m2, m2); }

    u64p acc2[4][4];
#pragma unroll
    for (int i = 0; i < 4; i++)
#pragma unroll
        for (int j = 0; j < 4; j++) acc2[i][j] = 0ull;
    int cnti[8] = {0, 0, 0, 0, 0, 0, 0, 0};

    for (int t = blockIdx.x; t < NT128; t += GXI) {
        const int tb = t * PB;
        __syncthreads();
        if (tid == 0) *flagp = 0;
        {   // single global read -> Xr (row) + Xt (transposed)
            int ploc = tid & 127, d0 = (tid >> 7) * 32;
            bool valid = (tb + ploc) < NPTS;
            const float4* src = (const float4*)(x + (size_t)(tb + ploc) * DIM + d0);
#pragma unroll
            for (int k = 0; k < 8; k++) {
                float4 v = valid ? src[k] : make_float4(0.f, 0.f, 0.f, 0.f);
                *(float4*)(Xr + ploc * XRS + d0 + 4 * k) = v;
                Xt[(d0 + 4 * k + 0) * XTS + ploc] = v.x;
                Xt[(d0 + 4 * k + 1) * XTS + ploc] = v.y;
                Xt[(d0 + 4 * k + 2) * XTS + ploc] = v.z;
                Xt[(d0 + 4 * k + 3) * XTS + ploc] = v.w;
            }
            if (tid < PB) x2s[tid] = ((tb + tid) < NPTS) ? g_x2[tb + tid] : -1e30f;
        }
        __syncthreads();

        u64p S2[8][4];
#pragma unroll
        for (int i = 0; i < 8; i++)
#pragma unroll
            for (int j = 0; j < 4; j++) S2[i][j] = 0ull;

#pragma unroll 8
        for (int dd = 0; dd < DIM; dd++) {
            float4 ca = *(const float4*)(Cs + dd * KB + ck0);
            float4 cb = *(const float4*)(Cs + dd * KB + ck0 + 4);
            float4 xa = *(const float4*)(Xt + dd * XTS + p0);
            float4 xb = *(const float4*)(Xt + dd * XTS + p0 + 4);
            u64p xp[4];
            PK2(xp[0], xa.x, xa.y); PK2(xp[1], xa.z, xa.w);
            PK2(xp[2], xb.x, xb.y); PK2(xp[3], xb.z, xb.w);
            float cv[8] = {ca.x, ca.y, ca.z, ca.w, cb.x, cb.y, cb.z, cb.w};
#pragma unroll
            for (int i = 0; i < 8; i++) {
                u64p cd; PK2(cd, cv[i], cv[i]);
#pragma unroll
                for (int j = 0; j < 4; j++) FMA2(S2[i][j], cd, xp[j], S2[i][j]);
            }
        }

        unsigned long long bits = 0ull;
#pragma unroll
        for (int jp = 0; jp < 4; jp++) {
            u64p x2p; PK2(x2p, x2s[p0 + 2 * jp], x2s[p0 + 2 * jp + 1]);
#pragma unroll
            for (int i = 0; i < 8; i++) {
                u64p tsum; ADD2(tsum, c2d[i], x2p);
                u64p d2;   FMA2(d2, neg2, S2[i][jp], tsum);
                float dlo, dhi; UPK2(dlo, dhi, d2);
                if (!(dlo < BW2)) bits |= 1ull << (i * 8 + 2 * jp);
                if (!(dhi < BW2)) bits |= 1ull << (i * 8 + 2 * jp + 1);
            }
        }
#pragma unroll
        for (int i = 0; i < 8; i++)
            cnti[i] += __popc((unsigned)((bits >> (i * 8)) & 0xFFull));

        unsigned bal = __ballot_sync(0xffffffffu, bits != 0ull);
        if (bal != 0u && (tid & 31) == 0) atomicOr(flagp, 1);
        __syncthreads();

        if (*flagp) {
            const int sw = tx & 7;
            const int colA = 4 * ((2 * ty) ^ sw);
            const int colB = 4 * ((2 * ty + 1) ^ sw);
#pragma unroll
            for (int jp = 0; jp < 4; jp++) {
                int j0 = 2 * jp, j1 = 2 * jp + 1;
                float4 a0, b0, a1, b1;
                a0.x = (float)((bits >> (0 * 8 + j0)) & 1ull);
                a0.y = (float)((bits >> (1 * 8 + j0)) & 1ull);
                a0.z = (float)((bits >> (2 * 8 + j0)) & 1ull);
                a0.w = (float)((bits >> (3 * 8 + j0)) & 1ull);
                b0.x = (float)((bits >> (4 * 8 + j0)) & 1ull);
                b0.y = (float)((bits >> (5 * 8 + j0)) & 1ull);
                b0.z = (float)((bits >> (6 * 8 + j0)) & 1ull);
                b0.w = (float)((bits >> (7 * 8 + j0)) & 1ull);
                a1.x = (float)((bits >> (0 * 8 + j1)) & 1ull);
                a1.y = (float)((bits >> (1 * 8 + j1)) & 1ull);
                a1.z = (float)((bits >> (2 * 8 + j1)) & 1ull);
                a1.w = (float)((bits >> (3 * 8 + j1)) & 1ull);
                b1.x = (float)((bits >> (4 * 8 + j1)) & 1ull);
                b1.y = (float)((bits >> (5 * 8 + j1)) & 1ull);
                b1.z = (float)((bits >> (6 * 8 + j1)) & 1ull);
                b1.w = (float)((bits >> (7 * 8 + j1)) & 1ull);
                int pA = p0 + j0, pB = p0 + j1;
                *(float4*)(Ms + pA * MSS + colA) = a0;
                *(float4*)(Ms + pA * MSS + colB) = b0;
                *(float4*)(Ms + pB * MSS + colA) = a1;
                *(float4*)(Ms + pB * MSS + colB) = b1;
            }
            __syncthreads();

#pragma unroll 4
            for (int p = 0; p < PB; p++) {
                const int sw2 = (p >> 3) & 7;
                float4 ma = *(const float4*)(Ms + p * MSS + 4 * ((2 * ty) ^ sw2));
                float4 mb = *(const float4*)(Ms + p * MSS + 4 * ((2 * ty + 1) ^ sw2));
                float4 xv = *(const float4*)(Xr + p * XRS + dq);
                u64p mp[4];
                PK2(mp[0], ma.x, ma.y); PK2(mp[1], ma.z, ma.w);
                PK2(mp[2], mb.x, mb.y); PK2(mp[3], mb.z, mb.w);
                u64p xd[4];
                PK2(xd[0], xv.x, xv.x); PK2(xd[1], xv.y, xv.y);
                PK2(xd[2], xv.z, xv.z); PK2(xd[3], xv.w, xv.w);
#pragma unroll
                for (int i2 = 0; i2 < 4; i2++)
#pragma unroll
                    for (int j = 0; j < 4; j++) FMA2(acc2[i2][j], mp[i2], xd[j], acc2[i2][j]);
            }
        }
    }

#pragma unroll
    for (int i2 = 0; i2 < 4; i2++)
#pragma unroll
        for (int j = 0; j < 4; j++) {
            float alo, ahi; UPK2(alo, ahi, acc2[i2][j]);
            atomicAdd(&g_acc[kb + ck0 + 2 * i2 + 0][dq + j], alo);
            atomicAdd(&g_acc[kb + ck0 + 2 * i2 + 1][dq + j], ahi);
        }
#pragma unroll
    for (int i = 0; i < 8; i++) {
        float v = (float)cnti[i];
#pragma unroll
        for (int off = 8; off > 0; off >>= 1)
            v += __shfl_down_sync(0xffffffffu, v, off, 16);
        if (tx == 0) atomicAdd(&g_cnt[kb + ck0 + i], v);
    }
}

// ------------------------------------------- persistent sparse iterations 1..9
// One grid-sync per iteration (per-iteration buffers remove the reset sync;
// redundant full updates remove the handoff sync). Early exit at fixed point.

static __device__ __forceinline__ void grid_sync() {
    __threadfence();
    __syncthreads();
    if (threadIdx.x == 0) {
        unsigned gen = g_bargen;
        if (atomicAdd(&g_barcnt, 1u) == SPB - 1) {
            g_barcnt = 0;
            __threadfence();
            g_bargen = gen + 1;
        } else {
            while (g_bargen == gen) { __nanosleep(32); }
        }
    }
    __syncthreads();
}

__global__ void __launch_bounds__(256) sparse_all(const float* __restrict__ x) {
    __shared__ float red[KC];
    __shared__ int chg;
    const int tid = threadIdx.x;
    const int gtid = blockIdx.x * 256 + tid;
    const int stride = SPB * 256;

    for (int it = 1; it < ITERS; it++) {
        const float* cc = &g_c[it & 1][0][0];

        // block-local cmax (identical across blocks)
        {
            const float4* cr = (const float4*)(cc + (size_t)tid * DIM);
            float c2 = 0.f;
#pragma unroll
            for (int q = 0; q < 16; q++) {
                float4 v = cr[q];
                c2 = fmaf(v.x, v.x, c2); c2 = fmaf(v.y, v.y, c2);
                c2 = fmaf(v.z, v.z, c2); c2 = fmaf(v.w, v.w, c2);
            }
            red[tid] = c2;
            if (tid == 0) chg = 0;
            __syncthreads();
            for (int s = 128; s > 0; s >>= 1) {
                if (tid < s) red[tid] = fmaxf(red[tid], red[tid + s]);
                __syncthreads();
            }
        }
        const float cmax = sqrtf(red[0]) + 1e-3f;
        float tthr = 12.0f - cmax - 1e-3f;
        const float thr2 = (tthr > 0.f) ? tthr * tthr : -1.0f;

        // candidate scan + exact exception check (records tileflags: union
        // over iterations = conservative superset of the it=9 set)
        for (int n = gtid; n < NPTS; n += stride) {
            const float x2 = g_x2[n];
            if (x2 < thr2) continue;
            g_tileflag[n >> 6] = 1;

            float xv[DIM];
            const float4* xr = (const float4*)(x + (size_t)n * DIM);
#pragma unroll
            for (int q = 0; q < 16; q++) {
                float4 v = xr[q];
                xv[4 * q + 0] = v.x; xv[4 * q + 1] = v.y;
                xv[4 * q + 2] = v.z; xv[4 * q + 3] = v.w;
            }
            for (int k = 0; k < KC; k++) {
                const float4* cr = (const float4*)(cc + (size_t)k * DIM);
                float dot = 0.f, c2 = 0.f;
#pragma unroll
                for (int q = 0; q < 16; q++) {
                    float4 cv = cr[q];
                    dot = fmaf(cv.x, xv[4 * q + 0], dot);
                    dot = fmaf(cv.y, xv[4 * q + 1], dot);
                    dot = fmaf(cv.z, xv[4 * q + 2], dot);
                    dot = fmaf(cv.w, xv[4 * q + 3], dot);
                    c2 = fmaf(cv.x, cv.x, c2); c2 = fmaf(cv.y, cv.y, c2);
                    c2 = fmaf(cv.z, cv.z, c2); c2 = fmaf(cv.w, cv.w, c2);
                }
                float d2 = c2 + x2 - 2.f * dot;
                if (!(d2 < BW2)) {
                    atomicAdd(&g_cnt2[it - 1][k], 1.0f);
#pragma unroll
                    for (int d = 0; d < DIM; d++)
                        atomicAdd(&g_acc2[it - 1][k][d], xv[d]);
                }
            }
        }

        grid_sync();   // all exception atomics of this iteration visible

        // redundant full update: every block computes ALL centers (identical
        // deterministic fp64 math -> identical bits -> identical exit decision)
        {
            double cnt = (double)NPTS - (double)g_cnt2[it - 1][tid];
            const float* accr = &g_acc2[it - 1][tid][0];
            const float* oldc = &g_c[it & 1][tid][0];
            float* newc = &g_c[(it + 1) & 1][tid][0];
            int diff = 0;
            for (int d = 0; d < DIM; d++) {
                double v = (g_sumx[d] - (double)accr[d]) / cnt;
                float nf = (float)v;
                if (__float_as_uint(nf) != __float_as_uint(oldc[d])) diff = 1;
                newc[d] = nf;
            }
            if (diff) chg = 1;
        }
        __syncthreads();   // update writes + chg visible block-wide
        if (!chg) break;   // fixed point: both center buffers now equal
    }
}

// ------------------------------------------- final masked argmin, f32x2
// 64 centers/CTA (S2[4][4] -> ~90 regs), 2 CTAs/SM without spills.

__global__ void __launch_bounds__(256, 2) final_kernel(const float* __restrict__ x) {
    extern __shared__ float sm[];
    float* Ct   = sm;                 // [64][64] c10 transposed
    float* c210 = Ct + 64 * FKB;      // [64]
    float* Xt   = c210 + FKB;         // [64][132]
    float* x2s  = Xt + 64 * XTS;      // [128]

    const int tid = threadIdx.x;
    const int ty = tid >> 4, tx = tid & 15;
    const int ck0 = ty * 4, p0 = tx * 8;
    const int kb = blockIdx.y * FKB;

    for (int e = tid; e < FKB * DIM; e += 256) {
        int ck = e & (FKB - 1), d = e >> 6;
        Ct[d * FKB + ck] = g_c[0][kb + ck][d];
    }
    __syncthreads();
    if (tid < FKB) {
        float s = 0.f;
#pragma unroll
        for (int d = 0; d < DIM; d++) { float a = Ct[d * FKB + tid]; s = fmaf(a, a, s); }
        c210[tid] = s;
    }
    __syncthreads();

    unsigned long long best[4];
#pragma unroll
    for (int i = 0; i < 4; i++) best[i] = ~0ull;

    for (int t = blockIdx.x; t < NT128; t += GXF) {
        const int tb = t * PB;
        __syncthreads();
        {
            int ploc = tid & 127, d0 = (tid >> 7) * 32;
            bool valid = (tb + ploc) < NPTS;
            const float4* src = (const float4*)(x + (size_t)(tb + ploc) * DIM + d0);
#pragma unroll
            for (int k = 0; k < 8; k++) {
                float4 v = valid ? src[k] : make_float4(0.f, 0.f, 0.f, 0.f);
                Xt[(d0 + 4 * k + 0) * XTS + ploc] = v.x;
                Xt[(d0 + 4 * k + 1) * XTS + ploc] = v.y;
                Xt[(d0 + 4 * k + 2) * XTS + ploc] = v.z;
                Xt[(d0 + 4 * k + 3) * XTS + ploc] = v.w;
            }
            if (tid < PB) x2s[tid] = ((tb + tid) < NPTS) ? g_x2[tb + tid] : 0.f;
        }
        __syncthreads();

        u64p S2[4][4];
#pragma unroll
        for (int i = 0; i < 4; i++)
#pragma unroll
            for (int j = 0; j < 4; j++) S2[i][j] = 0ull;

#pragma unroll 8
        for (int dd = 0; dd < DIM; dd++) {
            float4 ca = *(const float4*)(Ct + dd * FKB + ck0);
            float4 xa = *(const float4*)(Xt + dd * XTS + p0);
            float4 xb = *(const float4*)(Xt + dd * XTS + p0 + 4);
            u64p xp[4];
            PK2(xp[0], xa.x, xa.y); PK2(xp[1], xa.z, xa.w);
            PK2(xp[2], xb.x, xb.y); PK2(xp[3], xb.z, xb.w);
            float cv[4] = {ca.x, ca.y, ca.z, ca.w};
#pragma unroll
            for (int i = 0; i < 4; i++) {
                u64p cd; PK2(cd, cv[i], cv[i]);
#pragma unroll
                for (int j = 0; j < 4; j++) FMA2(S2[i][j], cd, xp[j], S2[i][j]);
            }
        }

        const int flagged = g_tileflag[2 * t] |
                            ((2 * t + 1 < NT64) ? g_tileflag[2 * t + 1] : 0);

#pragma unroll
        for (int jp = 0; jp < 4; jp++) {
            const int pA = p0 + 2 * jp, pB = pA + 1;
            const float xa2 = x2s[pA], xb2 = x2s[pB];
            const unsigned ia = (unsigned)(tb + pA), ib = (unsigned)(tb + pB);
#pragma unroll
            for (int i = 0; i < 4; i++) {
                float dlo, dhi; UPK2(dlo, dhi, S2[i][jp]);
                const float c2v = c210[ck0 + i];
                bool oka = true, okb = true;
                if (flagged) {
                    const float* c9r = &g_c[1][kb + ck0 + i][0];
                    float d9a = 0.f, d9b = 0.f, c29v = 0.f;
                    for (int dd = 0; dd < DIM; dd++) {
                        float cv9 = c9r[dd];
                        d9a = fmaf(cv9, Xt[dd * XTS + pA], d9a);
                        d9b = fmaf(cv9, Xt[dd * XTS + pB], d9b);
                        c29v = fmaf(cv9, cv9, c29v);
                    }
                    oka = fmaf(-2.f, d9a, c29v + xa2) < BW2;
                    okb = fmaf(-2.f, d9b, c29v + xb2) < BW2;
                }
                if (oka && ia < NPTS) {
                    float d2 = fmaxf(fmaf(-2.f, dlo, c2v + xa2), 0.f);
                    unsigned long long key =
                        ((unsigned long long)__float_as_uint(d2) << 32) | ia;
                    if (key < best[i]) best[i] = key;
                }
                if (okb && ib < NPTS) {
                    float d2 = fmaxf(fmaf(-2.f, dhi, c2v + xb2), 0.f);
                    unsigned long long key =
                        ((unsigned long long)__float_as_uint(d2) << 32) | ib;
                    if (key < best[i]) best[i] = key;
                }
            }
        }
    }

#pragma unroll
    for (int i = 0; i < 4; i++) {
        unsigned long long v = best[i];
#pragma unroll
        for (int off = 8; off > 0; off >>= 1) {
            unsigned long long o = __shfl_down_sync(0xffffffffu, v, off, 16);
            if (o < v) v = o;
        }
        if (tx == 0) atomicMin(&g_best[kb + ck0 + i], v);
    }
}

// ---------------------------------------------------------------- epilogue

__global__ void zero_out(float* out, int n) {
    int i = blockIdx.x * blockDim.x + threadIdx.x;
    if (i < n) out[i] = 0.f;
}

__global__ void finish_kernel(float* __restrict__ out, const float* __restrict__ x,
                              int out_size) {
    int k = blockIdx.x, d = threadIdx.x;
    if (out_size >= KC * DIM)
        out[k * DIM + d] = g_c[0][k][d];
    unsigned long long b = g_best[k];
    unsigned idx = (b == ~0ull) ? 0u : (unsigned)(b & 0xffffffffu);
    if (out_size >= 2 * KC * DIM)
        out[KC * DIM + k * DIM + d] = x[(size_t)idx * DIM + d];
    if (d == 0 && out_size >= 2 * KC * DIM + KC)
        out[2 * KC * DIM + k] = (float)idx;
}

// ---------------------------------------------------------------- launcher

extern "C" void kernel_launch(void* const* d_in, const int* in_sizes, int n_in,
                              void* d_out, int out_size) {
    const float* x = (const float*)d_in[0];
    const void* seed = d_in[1];
    float* out = (float*)d_out;
    (void)in_sizes; (void)n_in;

    const size_t iterSmem = (size_t)(64 * KB + KB + 64 * XTS + PB * XRS + PB * MSS + PB + 16)
                            * sizeof(float);
    const size_t finalSmem = (size_t)(64 * FKB + FKB + 64 * XTS + PB) * sizeof(float);
    cudaFuncSetAttribute(iter_kernel,  cudaFuncAttributeMaxDynamicSharedMemorySize, (int)iterSmem);
    cudaFuncSetAttribute(final_kernel, cudaFuncAttributeMaxDynamicSharedMemorySize, (int)finalSmem);

    detect_kernel<<<1, 128>>>(seed);
    x2_kernel<<<(NPTS + 255) / 256, 256>>>(x);
    seed_kernel<<<KC, DIM>>>(x, seed);

    iter_kernel<<<dim3(GXI, KC / KB), 256, iterSmem>>>(x, 0);
    update_kernel<<<KC, DIM>>>(0);

    sparse_all<<<SPB, 256>>>(x);

    final_kernel<<<dim3(GXF, KC / FKB), 256, finalSmem>>>(x);

    if (out_size > 0)
        zero_out<<<(out_size + 255) / 256, 256>>>(out, out_size);
    finish_kernel<<<KC, DIM>>>(out, x, out_size);
}

// round 10
// speedup vs baseline: 1.0389x; 1.0389x over previous
#include <cuda_runtime.h>
#include <cuda_bf16.h>
#include <stdint.h>

#define NPTS 200000
#define DIM 64
#define KC 256
#define BW2 144.0f
#define ITERS 10

#define KB 128
#define PB 128
#define NT128 1563
#define GXI 74
#define GXF 74
#define XTS 132
#define XRS 68
#define MSS 132
#define NT64 3125
#define SPB 148

typedef unsigned long long u64p;
#define PK2(d, lo, hi) asm("mov.b64 %0, {%1, %2};" : "=l"(d) : "f"(lo), "f"(hi))
#define UPK2(lo, hi, s) asm("mov.b64 {%0, %1}, %2;" : "=f"(lo), "=f"(hi) : "l"(s))
#define FMA2(d, a, b, c) asm("fma.rn.f32x2 %0, %1, %2, %3;" : "=l"(d) : "l"(a), "l"(b), "l"(c))
#define ADD2(d, a, b) asm("add.rn.f32x2 %0, %1, %2;" : "=l"(d) : "l"(a), "l"(b))

__device__ float g_c[2][KC][DIM];
__device__ float g_acc[KC][DIM];
__device__ float g_cnt[KC];
__device__ float g_acc2[ITERS - 1][KC][DIM];
__device__ float g_cnt2[ITERS - 1][KC];
__device__ double g_sumx[DIM];
__device__ float g_x2[NPTS];
__device__ unsigned long long g_best[KC];
__device__ int g_seed64;
__device__ int g_tileflag[NT64];
__device__ unsigned g_barcnt;
__device__ volatile unsigned g_bargen;

// ------------------------------------------------- prologue kernels

__global__ void detect_kernel(const void* __restrict__ seed) {
    __shared__ int bad;
    if (threadIdx.x == 0) bad = 0;
    if (threadIdx.x < DIM) g_sumx[threadIdx.x] = 0.0;
    __syncthreads();
    unsigned long long v = ((const unsigned long long*)seed)[threadIdx.x];
    if (v >= (unsigned long long)NPTS) atomicOr(&bad, 1);
    __syncthreads();
    if (threadIdx.x == 0) g_seed64 = bad ? 0 : 1;
}

__global__ void x2_kernel(const float* __restrict__ x) {
    __shared__ float wsum[8][DIM];
    const int tid = threadIdx.x;
    const int n = blockIdx.x * 256 + tid;
    const int lane = tid & 31, wid = tid >> 5;
    const bool valid = n < NPTS;
    const float4* r = (const float4*)(x + (size_t)n * DIM);

    float x2 = 0.f;
#pragma unroll
    for (int q = 0; q < 16; q++) {
        float4 v = valid ? r[q] : make_float4(0.f, 0.f, 0.f, 0.f);
        x2 = fmaf(v.x, v.x, x2); x2 = fmaf(v.y, v.y, x2);
        x2 = fmaf(v.z, v.z, x2); x2 = fmaf(v.w, v.w, x2);
#pragma unroll
        for (int off = 16; off > 0; off >>= 1) {
            v.x += __shfl_xor_sync(0xffffffffu, v.x, off);
            v.y += __shfl_xor_sync(0xffffffffu, v.y, off);
            v.z += __shfl_xor_sync(0xffffffffu, v.z, off);
            v.w += __shfl_xor_sync(0xffffffffu, v.w, off);
        }
        if (lane == 0) *(float4*)&wsum[wid][4 * q] = v;
    }
    if (valid) g_x2[n] = x2;
    if (n < NT64) g_tileflag[n] = 0;
    if (n < (ITERS - 1) * KC * DIM) ((float*)g_acc2)[n] = 0.f;
    if (n < (ITERS - 1) * KC) ((float*)g_cnt2)[n] = 0.f;
    __syncthreads();
    if (tid < DIM) {
        float tot = 0.f;
#pragma unroll
        for (int w = 0; w < 8; w++) tot += wsum[w][tid];
        atomicAdd(&g_sumx[tid], (double)tot);
    }
}

__global__ void seed_kernel(const float* __restrict__ x, const void* __restrict__ seedraw) {
    int k = blockIdx.x, d = threadIdx.x;
    long long idx;
    if (g_seed64) idx = ((const long long*)seedraw)[k];
    else          idx = (long long)(((const int*)seedraw)[k]);
    g_c[0][k][d] = x[idx * DIM + d];
    g_acc[k][d] = 0.f;
    if (d == 0) { g_cnt[k] = 0.f; g_best[k] = ~0ull; }
}

__global__ void update_kernel(int it) {
    int k = blockIdx.x, d = threadIdx.x;
    double cnt = (double)NPTS - (double)g_cnt[k];
    double v = (g_sumx[d] - (double)g_acc[k][d]) / cnt;
    __syncthreads();
    g_c[(it + 1) & 1][k][d] = (float)v;
}

// ------------------------------------------- dense iteration (it=0)
// Software-pipelined: tile t+1's global loads issue before tile t's compute.

__global__ void __launch_bounds__(256, 1) iter_kernel(const float* __restrict__ x, int it) {
    extern __shared__ float smem[];
    float* Cs  = smem;
    float* c2s = Cs + 64 * KB;
    float* Xt  = c2s + KB;
    float* Xr  = Xt + 64 * XTS;
    float* Ms  = Xr + PB * XRS;
    float* x2s = Ms + PB * MSS;
    int* flagp = (int*)(x2s + PB);

    const int tid = threadIdx.x;
    const int ty = tid >> 4, tx = tid & 15;
    const int ck0 = ty * 8, p0 = tx * 8, dq = tx * 4;
    const int kb = blockIdx.y * KB;
    const int ploc = tid & 127, d0 = (tid >> 7) * 32;
    const float* cin = &g_c[it & 1][0][0];

    for (int e = tid; e < KB * DIM; e += 256) {
        int ck = e & (KB - 1), d = e >> 7;
        Cs[d * KB + ck] = cin[(size_t)(kb + ck) * DIM + d];
    }
    __syncthreads();
    if (tid < KB) {
        float s = 0.f;
#pragma unroll
        for (int d = 0; d < DIM; d++) { float c = Cs[d * KB + tid]; s = fmaf(c, c, s); }
        c2s[tid] = s;
    }
    __syncthreads();

    u64p c2d[8];
#pragma unroll
    for (int i = 0; i < 8; i++) { float v = c2s[ck0 + i]; PK2(c2d[i], v, v); }
    u64p neg2; { float m2 = -2.0f; PK2(neg2, m2, m2); }

    u64p acc2[4][4];
#pragma unroll
    for (int i = 0; i < 4; i++)
#pragma unroll
        for (int j = 0; j < 4; j++) acc2[i][j] = 0ull;
    int cnti[8] = {0, 0, 0, 0, 0, 0, 0, 0};

    // prefetch first tile
    float4 pf[8];
    float pfx2 = 0.f;
    {
        const int tb = blockIdx.x * PB;
        bool valid = (tb + ploc) < NPTS;
        const float4* src = (const float4*)(x + (size_t)(tb + ploc) * DIM + d0);
#pragma unroll
        for (int k = 0; k < 8; k++)
            pf[k] = valid ? src[k] : make_float4(0.f, 0.f, 0.f, 0.f);
        if (tid < PB) pfx2 = ((tb + tid) < NPTS) ? g_x2[tb + tid] : -1e30f;
    }

    for (int t = blockIdx.x; t < NT128; t += GXI) {
        __syncthreads();           // previous tile's consumers done
        if (tid == 0) *flagp = 0;
        {   // stage prefetched regs -> Xr + Xt
#pragma unroll
            for (int k = 0; k < 8; k++) {
                float4 v = pf[k];
                *(float4*)(Xr + ploc * XRS + d0 + 4 * k) = v;
                Xt[(d0 + 4 * k + 0) * XTS + ploc] = v.x;
                Xt[(d0 + 4 * k + 1) * XTS + ploc] = v.y;
                Xt[(d0 + 4 * k + 2) * XTS + ploc] = v.z;
                Xt[(d0 + 4 * k + 3) * XTS + ploc] = v.w;
            }
            if (tid < PB) x2s[tid] = pfx2;
        }
        __syncthreads();

        // prefetch NEXT tile while computing this one
        const int tn = t + GXI;
        if (tn < NT128) {
            const int tbn = tn * PB;
            bool valid = (tbn + ploc) < NPTS;
            const float4* src = (const float4*)(x + (size_t)(tbn + ploc) * DIM + d0);
#pragma unroll
            for (int k = 0; k < 8; k++)
                pf[k] = valid ? src[k] : make_float4(0.f, 0.f, 0.f, 0.f);
            if (tid < PB) pfx2 = ((tbn + tid) < NPTS) ? g_x2[tbn + tid] : -1e30f;
        }

        u64p S2[8][4];
#pragma unroll
        for (int i = 0; i < 8; i++)
#pragma unroll
            for (int j = 0; j < 4; j++) S2[i][j] = 0ull;

#pragma unroll 8
        for (int dd = 0; dd < DIM; dd++) {
            float4 ca = *(const float4*)(Cs + dd * KB + ck0);
            float4 cb = *(const float4*)(Cs + dd * KB + ck0 + 4);
            float4 xa = *(const float4*)(Xt + dd * XTS + p0);
            float4 xb = *(const float4*)(Xt + dd * XTS + p0 + 4);
            u64p xp[4];
            PK2(xp[0], xa.x, xa.y); PK2(xp[1], xa.z, xa.w);
            PK2(xp[2], xb.x, xb.y); PK2(xp[3], xb.z, xb.w);
            float cv[8] = {ca.x, ca.y, ca.z, ca.w, cb.x, cb.y, cb.z, cb.w};
#pragma unroll
            for (int i = 0; i < 8; i++) {
                u64p cd; PK2(cd, cv[i], cv[i]);
#pragma unroll
                for (int j = 0; j < 4; j++) FMA2(S2[i][j], cd, xp[j], S2[i][j]);
            }
        }

        unsigned long long bits = 0ull;
#pragma unroll
        for (int jp = 0; jp < 4; jp++) {
            u64p x2p; PK2(x2p, x2s[p0 + 2 * jp], x2s[p0 + 2 * jp + 1]);
#pragma unroll
            for (int i = 0; i < 8; i++) {
                u64p tsum; ADD2(tsum, c2d[i], x2p);
                u64p d2;   FMA2(d2, neg2, S2[i][jp], tsum);
                float dlo, dhi; UPK2(dlo, dhi, d2);
                if (!(dlo < BW2)) bits |= 1ull << (i * 8 + 2 * jp);
                if (!(dhi < BW2)) bits |= 1ull << (i * 8 + 2 * jp + 1);
            }
        }
#pragma unroll
        for (int i = 0; i < 8; i++)
            cnti[i] += __popc((unsigned)((bits >> (i * 8)) & 0xFFull));

        unsigned bal = __ballot_sync(0xffffffffu, bits != 0ull);
        if (bal != 0u && (tid & 31) == 0) atomicOr(flagp, 1);
        __syncthreads();

        if (*flagp) {
            const int sw = tx & 7;
            const int colA = 4 * ((2 * ty) ^ sw);
            const int colB = 4 * ((2 * ty + 1) ^ sw);
#pragma unroll
            for (int jp = 0; jp < 4; jp++) {
                int j0 = 2 * jp, j1 = 2 * jp + 1;
                float4 a0, b0, a1, b1;
                a0.x = (float)((bits >> (0 * 8 + j0)) & 1ull);
                a0.y = (float)((bits >> (1 * 8 + j0)) & 1ull);
                a0.z = (float)((bits >> (2 * 8 + j0)) & 1ull);
                a0.w = (float)((bits >> (3 * 8 + j0)) & 1ull);
                b0.x = (float)((bits >> (4 * 8 + j0)) & 1ull);
                b0.y = (float)((bits >> (5 * 8 + j0)) & 1ull);
                b0.z = (float)((bits >> (6 * 8 + j0)) & 1ull);
                b0.w = (float)((bits >> (7 * 8 + j0)) & 1ull);
                a1.x = (float)((bits >> (0 * 8 + j1)) & 1ull);
                a1.y = (float)((bits >> (1 * 8 + j1)) & 1ull);
                a1.z = (float)((bits >> (2 * 8 + j1)) & 1ull);
                a1.w = (float)((bits >> (3 * 8 + j1)) & 1ull);
                b1.x = (float)((bits >> (4 * 8 + j1)) & 1ull);
                b1.y = (float)((bits >> (5 * 8 + j1)) & 1ull);
                b1.z = (float)((bits >> (6 * 8 + j1)) & 1ull);
                b1.w = (float)((bits >> (7 * 8 + j1)) & 1ull);
                int pA = p0 + j0, pB = p0 + j1;
                *(float4*)(Ms + pA * MSS + colA) = a0;
                *(float4*)(Ms + pA * MSS + colB) = b0;
                *(float4*)(Ms + pB * MSS + colA) = a1;
                *(float4*)(Ms + pB * MSS + colB) = b1;
            }
            __syncthreads();

#pragma unroll 4
            for (int p = 0; p < PB; p++) {
                const int sw2 = (p >> 3) & 7;
                float4 ma = *(const float4*)(Ms + p * MSS + 4 * ((2 * ty) ^ sw2));
                float4 mb = *(const float4*)(Ms + p * MSS + 4 * ((2 * ty + 1) ^ sw2));
                float4 xv = *(const float4*)(Xr + p * XRS + dq);
                u64p mp[4];
                PK2(mp[0], ma.x, ma.y); PK2(mp[1], ma.z, ma.w);
                PK2(mp[2], mb.x, mb.y); PK2(mp[3], mb.z, mb.w);
                u64p xd[4];
                PK2(xd[0], xv.x, xv.x); PK2(xd[1], xv.y, xv.y);
                PK2(xd[2], xv.z, xv.z); PK2(xd[3], xv.w, xv.w);
#pragma unroll
                for (int i2 = 0; i2 < 4; i2++)
#pragma unroll
                    for (int j = 0; j < 4; j++) FMA2(acc2[i2][j], mp[i2], xd[j], acc2[i2][j]);
            }
        }
    }

#pragma unroll
    for (int i2 = 0; i2 < 4; i2++)
#pragma unroll
        for (int j = 0; j < 4; j++) {
            float alo, ahi; UPK2(alo, ahi, acc2[i2][j]);
            atomicAdd(&g_acc[kb + ck0 + 2 * i2 + 0][dq + j], alo);
            atomicAdd(&g_acc[kb + ck0 + 2 * i2 + 1][dq + j], ahi);
        }
#pragma unroll
    for (int i = 0; i < 8; i++) {
        float v = (float)cnti[i];
#pragma unroll
        for (int off = 8; off > 0; off >>= 1)
            v += __shfl_down_sync(0xffffffffu, v, off, 16);
        if (tx == 0) atomicAdd(&g_cnt[kb + ck0 + i], v);
    }
}

// ------------------------------------------- persistent sparse iterations 1..9

static __device__ __forceinline__ void grid_sync() {
    __threadfence();
    __syncthreads();
    if (threadIdx.x == 0) {
        unsigned gen = g_bargen;
        if (atomicAdd(&g_barcnt, 1u) == SPB - 1) {
            g_barcnt = 0;
            __threadfence();
            g_bargen = gen + 1;
        } else {
            while (g_bargen == gen) { __nanosleep(32); }
        }
    }
    __syncthreads();
}

__global__ void __launch_bounds__(256) sparse_all(const float* __restrict__ x) {
    __shared__ float red[KC];
    __shared__ int chg;
    const int tid = threadIdx.x;
    const int gtid = blockIdx.x * 256 + tid;
    const int stride = SPB * 256;

    for (int it = 1; it < ITERS; it++) {
        const float* cc = &g_c[it & 1][0][0];
        {
            const float4* cr = (const float4*)(cc + (size_t)tid * DIM);
            float c2 = 0.f;
#pragma unroll
            for (int q = 0; q < 16; q++) {
                float4 v = cr[q];
                c2 = fmaf(v.x, v.x, c2); c2 = fmaf(v.y, v.y, c2);
                c2 = fmaf(v.z, v.z, c2); c2 = fmaf(v.w, v.w, c2);
            }
            red[tid] = c2;
            if (tid == 0) chg = 0;
            __syncthreads();
            for (int s = 128; s > 0; s >>= 1) {
                if (tid < s) red[tid] = fmaxf(red[tid], red[tid + s]);
                __syncthreads();
            }
        }
        const float cmax = sqrtf(red[0]) + 1e-3f;
        float tthr = 12.0f - cmax - 1e-3f;
        const float thr2 = (tthr > 0.f) ? tthr * tthr : -1.0f;

        for (int n = gtid; n < NPTS; n += stride) {
            const float x2 = g_x2[n];
            if (x2 < thr2) continue;
            g_tileflag[n >> 6] = 1;

            float xv[DIM];
            const float4* xr = (const float4*)(x + (size_t)n * DIM);
#pragma unroll
            for (int q = 0; q < 16; q++) {
                float4 v = xr[q];
                xv[4 * q + 0] = v.x; xv[4 * q + 1] = v.y;
                xv[4 * q + 2] = v.z; xv[4 * q + 3] = v.w;
            }
            for (int k = 0; k < KC; k++) {
                const float4* cr = (const float4*)(cc + (size_t)k * DIM);
                float dot = 0.f, c2 = 0.f;
#pragma unroll
                for (int q = 0; q < 16; q++) {
                    float4 cv = cr[q];
                    dot = fmaf(cv.x, xv[4 * q + 0], dot);
                    dot = fmaf(cv.y, xv[4 * q + 1], dot);
                    dot = fmaf(cv.z, xv[4 * q + 2], dot);
                    dot = fmaf(cv.w, xv[4 * q + 3], dot);
                    c2 = fmaf(cv.x, cv.x, c2); c2 = fmaf(cv.y, cv.y, c2);
                    c2 = fmaf(cv.z, cv.z, c2); c2 = fmaf(cv.w, cv.w, c2);
                }
                float d2 = c2 + x2 - 2.f * dot;
                if (!(d2 < BW2)) {
                    atomicAdd(&g_cnt2[it - 1][k], 1.0f);
#pragma unroll
                    for (int d = 0; d < DIM; d++)
                        atomicAdd(&g_acc2[it - 1][k][d], xv[d]);
                }
            }
        }

        grid_sync();

        {
            double cnt = (double)NPTS - (double)g_cnt2[it - 1][tid];
            const float* accr = &g_acc2[it - 1][tid][0];
            const float* oldc = &g_c[it & 1][tid][0];
            float* newc = &g_c[(it + 1) & 1][tid][0];
            int diff = 0;
            for (int d = 0; d < DIM; d++) {
                double v = (g_sumx[d] - (double)accr[d]) / cnt;
                float nf = (float)v;
                if (__float_as_uint(nf) != __float_as_uint(oldc[d])) diff = 1;
                newc[d] = nf;
            }
            if (diff) chg = 1;
        }
        __syncthreads();
        if (!chg) break;
    }
}

// ------------------------------------------- final masked argmin, f32x2
// KB=128 centers/CTA (2 X passes), (256,1) -> no spills, prefetch pipeline.

__global__ void __launch_bounds__(256, 1) final_kernel(const float* __restrict__ x) {
    extern __shared__ float sm[];
    float* Ct   = sm;                 // [64][128]
    float* c210 = Ct + 64 * KB;       // [128]
    float* Xt   = c210 + KB;          // [64][132]
    float* x2s  = Xt + 64 * XTS;      // [128]

    const int tid = threadIdx.x;
    const int ty = tid >> 4, tx = tid & 15;
    const int ck0 = ty * 8, p0 = tx * 8;
    const int kb = blockIdx.y * KB;
    const int ploc = tid & 127, d0 = (tid >> 7) * 32;

    for (int e = tid; e < KB * DIM; e += 256) {
        int ck = e & (KB - 1), d = e >> 7;
        Ct[d * KB + ck] = g_c[0][kb + ck][d];
    }
    __syncthreads();
    if (tid < KB) {
        float s = 0.f;
#pragma unroll
        for (int d = 0; d < DIM; d++) { float a = Ct[d * KB + tid]; s = fmaf(a, a, s); }
        c210[tid] = s;
    }
    __syncthreads();

    unsigned long long best[8];
#pragma unroll
    for (int i = 0; i < 8; i++) best[i] = ~0ull;

    float4 pf[8];
    float pfx2 = 0.f;
    {
        const int tb = blockIdx.x * PB;
        bool valid = (tb + ploc) < NPTS;
        const float4* src = (const float4*)(x + (size_t)(tb + ploc) * DIM + d0);
#pragma unroll
        for (int k = 0; k < 8; k++)
            pf[k] = valid ? src[k] : make_float4(0.f, 0.f, 0.f, 0.f);
        if (tid < PB) pfx2 = ((tb + tid) < NPTS) ? g_x2[tb + tid] : 0.f;
    }

    for (int t = blockIdx.x; t < NT128; t += GXF) {
        const int tb = t * PB;
        __syncthreads();
        {
#pragma unroll
            for (int k = 0; k < 8; k++) {
                float4 v = pf[k];
                Xt[(d0 + 4 * k + 0) * XTS + ploc] = v.x;
                Xt[(d0 + 4 * k + 1) * XTS + ploc] = v.y;
                Xt[(d0 + 4 * k + 2) * XTS + ploc] = v.z;
                Xt[(d0 + 4 * k + 3) * XTS + ploc] = v.w;
            }
            if (tid < PB) x2s[tid] = pfx2;
        }
        __syncthreads();

        const int tn = t + GXF;
        if (tn < NT128) {
            const int tbn = tn * PB;
            bool valid = (tbn + ploc) < NPTS;
            const float4* src = (const float4*)(x + (size_t)(tbn + ploc) * DIM + d0);
#pragma unroll
            for (int k = 0; k < 8; k++)
                pf[k] = valid ? src[k] : make_float4(0.f, 0.f, 0.f, 0.f);
            if (tid < PB) pfx2 = ((tbn + tid) < NPTS) ? g_x2[tbn + tid] : 0.f;
        }

        u64p S2[8][4];
#pragma unroll
        for (int i = 0; i < 8; i++)
#pragma unroll
            for (int j = 0; j < 4; j++) S2[i][j] = 0ull;

#pragma unroll 8
        for (int dd = 0; dd < DIM; dd++) {
            float4 ca = *(const float4*)(Ct + dd * KB + ck0);
            float4 cb = *(const float4*)(Ct + dd * KB + ck0 + 4);
            float4 xa = *(const float4*)(Xt + dd * XTS + p0);
            float4 xb = *(const float4*)(Xt + dd * XTS + p0 + 4);
            u64p xp[4];
            PK2(xp[0], xa.x, xa.y); PK2(xp[1], xa.z, xa.w);
            PK2(xp[2], xb.x, xb.y); PK2(xp[3], xb.z, xb.w);
            float cv[8] = {ca.x, ca.y, ca.z, ca.w, cb.x, cb.y, cb.z, cb.w};
#pragma unroll
            for (int i = 0; i < 8; i++) {
                u64p cd; PK2(cd, cv[i], cv[i]);
#pragma unroll
                for (int j = 0; j < 4; j++) FMA2(S2[i][j], cd, xp[j], S2[i][j]);
            }
        }

        const int flagged = g_tileflag[2 * t] |
                            ((2 * t + 1 < NT64) ? g_tileflag[2 * t + 1] : 0);

#pragma unroll
        for (int jp = 0; jp < 4; jp++) {
            const int pA = p0 + 2 * jp, pB = pA + 1;
            const float xa2 = x2s[pA], xb2 = x2s[pB];
            const unsigned ia = (unsigned)(tb + pA), ib = (unsigned)(tb + pB);
#pragma unroll
            for (int i = 0; i < 8; i++) {
                float dlo, dhi; UPK2(dlo, dhi, S2[i][jp]);
                const float c2v = c210[ck0 + i];
                bool oka = true, okb = true;
                if (flagged) {
                    const float* c9r = &g_c[1][kb + ck0 + i][0];
                    float d9a = 0.f, d9b = 0.f, c29v = 0.f;
                    for (int dd = 0; dd < DIM; dd++) {
                        float cv9 = c9r[dd];
                        d9a = fmaf(cv9, Xt[dd * XTS + pA], d9a);
                        d9b = fmaf(cv9, Xt[dd * XTS + pB], d9b);
                        c29v = fmaf(cv9, cv9, c29v);
                    }
                    oka = fmaf(-2.f, d9a, c29v + xa2) < BW2;
                    okb = fmaf(-2.f, d9b, c29v + xb2) < BW2;
                }
                if (oka && ia < NPTS) {
                    float d2 = fmaxf(fmaf(-2.f, dlo, c2v + xa2), 0.f);
                    unsigned long long key =
                        ((unsigned long long)__float_as_uint(d2) << 32) | ia;
                    if (key < best[i]) best[i] = key;
                }
                if (okb && ib < NPTS) {
                    float d2 = fmaxf(fmaf(-2.f, dhi, c2v + xb2), 0.f);
                    unsigned long long key =
                        ((unsigned long long)__float_as_uint(d2) << 32) | ib;
                    if (key < best[i]) best[i] = key;
                }
            }
        }
    }

#pragma unroll
    for (int i = 0; i < 8; i++) {
        unsigned long long v = best[i];
#pragma unroll
        for (int off = 8; off > 0; off >>= 1) {
            unsigned long long o = __shfl_down_sync(0xffffffffu, v, off, 16);
            if (o < v) v = o;
        }
        if (tx == 0) atomicMin(&g_best[kb + ck0 + i], v);
    }
}

// ---------------------------------------------------------------- epilogue

__global__ void zero_out(float* out, int n) {
    int i = blockIdx.x * blockDim.x + threadIdx.x;
    if (i < n) out[i] = 0.f;
}

__global__ void finish_kernel(float* __restrict__ out, const float* __restrict__ x,
                              int out_size) {
    int k = blockIdx.x, d = threadIdx.x;
    if (out_size >= KC * DIM)
        out[k * DIM + d] = g_c[0][k][d];
    unsigned long long b = g_best[k];
    unsigned idx = (b == ~0ull) ? 0u : (unsigned)(b & 0xffffffffu);
    if (out_size >= 2 * KC * DIM)
        out[KC * DIM + k * DIM + d] = x[(size_t)idx * DIM + d];
    if (d == 0 && out_size >= 2 * KC * DIM + KC)
        out[2 * KC * DIM + k] = (float)idx;
}

// ---------------------------------------------------------------- launcher

extern "C" void kernel_launch(void* const* d_in, const int* in_sizes, int n_in,
                              void* d_out, int out_size) {
    const float* x = (const float*)d_in[0];
    const void* seed = d_in[1];
    float* out = (float*)d_out;
    (void)in_sizes; (void)n_in;

    const size_t iterSmem = (size_t)(64 * KB + KB + 64 * XTS + PB * XRS + PB * MSS + PB + 16)
                            * sizeof(float);
    const size_t finalSmem = (size_t)(64 * KB + KB + 64 * XTS + PB) * sizeof(float);
    cudaFuncSetAttribute(iter_kernel,  cudaFuncAttributeMaxDynamicSharedMemorySize, (int)iterSmem);
    cudaFuncSetAttribute(final_kernel, cudaFuncAttributeMaxDynamicSharedMemorySize, (int)finalSmem);

    detect_kernel<<<1, 128>>>(seed);
    x2_kernel<<<(NPTS + 255) / 256, 256>>>(x);
    seed_kernel<<<KC, DIM>>>(x, seed);

    iter_kernel<<<dim3(GXI, KC / KB), 256, iterSmem>>>(x, 0);
    update_kernel<<<KC, DIM>>>(0);

    sparse_all<<<SPB, 256>>>(x);

    final_kernel<<<dim3(GXF, KC / KB), 256, finalSmem>>>(x);

    if (out_size > 0)
        zero_out<<<(out_size + 255) / 256, 256>>>(out, out_size);
    finish_kernel<<<KC, DIM>>>(out, x, out_size);
}

// round 11
// speedup vs baseline: 1.1928x; 1.1482x over previous
#include <cuda_runtime.h>
#include <cuda_bf16.h>
#include <stdint.h>

#define NPTS 200000
#define DIM 64
#define KC 256
#define BW2 144.0f
#define ITERS 10

#define KB 128
#define PB 128
#define NT128 1563
#define GXI 74
#define GXF 148
#define XTS 132
#define XRS 68
#define MSS 132
#define NT64 3125
#define SPB 148

typedef unsigned long long u64p;
#define PK2(d, lo, hi) asm("mov.b64 %0, {%1, %2};" : "=l"(d) : "f"(lo), "f"(hi))
#define UPK2(lo, hi, s) asm("mov.b64 {%0, %1}, %2;" : "=f"(lo), "=f"(hi) : "l"(s))
#define FMA2(d, a, b, c) asm("fma.rn.f32x2 %0, %1, %2, %3;" : "=l"(d) : "l"(a), "l"(b), "l"(c))
#define ADD2(d, a, b) asm("add.rn.f32x2 %0, %1, %2;" : "=l"(d) : "l"(a), "l"(b))

__device__ float g_c[2][KC][DIM];
__device__ float g_acc[KC][DIM];
__device__ float g_cnt[KC];
__device__ double g_sumx[DIM];
__device__ float g_x2[NPTS];
__device__ unsigned long long g_best[KC];
__device__ int g_seed64;
__device__ int g_tileflag[NT64];
__device__ int g_chgA[ITERS];
__device__ unsigned g_barcnt;
__device__ volatile unsigned g_bargen;

// ------------------------------------------------- prologue kernels

__global__ void detect_kernel(const void* __restrict__ seed) {
    __shared__ int bad;
    if (threadIdx.x == 0) bad = 0;
    if (threadIdx.x < DIM) g_sumx[threadIdx.x] = 0.0;
    __syncthreads();
    unsigned long long v = ((const unsigned long long*)seed)[threadIdx.x];
    if (v >= (unsigned long long)NPTS) atomicOr(&bad, 1);
    __syncthreads();
    if (threadIdx.x == 0) g_seed64 = bad ? 0 : 1;
}

// x2 per point + fused column sum + flag/changelog zeroing
__global__ void x2_kernel(const float* __restrict__ x) {
    __shared__ float wsum[8][DIM];
    const int tid = threadIdx.x;
    const int n = blockIdx.x * 256 + tid;
    const int lane = tid & 31, wid = tid >> 5;
    const bool valid = n < NPTS;
    const float4* r = (const float4*)(x + (size_t)n * DIM);

    float x2 = 0.f;
#pragma unroll
    for (int q = 0; q < 16; q++) {
        float4 v = valid ? r[q] : make_float4(0.f, 0.f, 0.f, 0.f);
        x2 = fmaf(v.x, v.x, x2); x2 = fmaf(v.y, v.y, x2);
        x2 = fmaf(v.z, v.z, x2); x2 = fmaf(v.w, v.w, x2);
#pragma unroll
        for (int off = 16; off > 0; off >>= 1) {
            v.x += __shfl_xor_sync(0xffffffffu, v.x, off);
            v.y += __shfl_xor_sync(0xffffffffu, v.y, off);
            v.z += __shfl_xor_sync(0xffffffffu, v.z, off);
            v.w += __shfl_xor_sync(0xffffffffu, v.w, off);
        }
        if (lane == 0) *(float4*)&wsum[wid][4 * q] = v;
    }
    if (valid) g_x2[n] = x2;
    if (n < NT64) g_tileflag[n] = 0;
    if (n < ITERS) g_chgA[n] = 0;
    __syncthreads();
    if (tid < DIM) {
        float tot = 0.f;
#pragma unroll
        for (int w = 0; w < 8; w++) tot += wsum[w][tid];
        atomicAdd(&g_sumx[tid], (double)tot);
    }
}

__global__ void seed_kernel(const float* __restrict__ x, const void* __restrict__ seedraw) {
    int k = blockIdx.x, d = threadIdx.x;
    long long idx;
    if (g_seed64) idx = ((const long long*)seedraw)[k];
    else          idx = (long long)(((const int*)seedraw)[k]);
    g_c[0][k][d] = x[idx * DIM + d];
    g_acc[k][d] = 0.f;
    if (d == 0) { g_cnt[k] = 0.f; g_best[k] = ~0ull; }
}

__global__ void update_kernel(int it) {
    int k = blockIdx.x, d = threadIdx.x;
    double cnt = (double)NPTS - (double)g_cnt[k];
    double v = (g_sumx[d] - (double)g_acc[k][d]) / cnt;
    __syncthreads();
    g_c[(it + 1) & 1][k][d] = (float)v;
    g_acc[k][d] = 0.f;
    if (d == 0) g_cnt[k] = 0.f;
}

// ------------------------------------------- dense iteration (it=0)
// Software-pipelined (round-10 version, measured 378us).

__global__ void __launch_bounds__(256, 1) iter_kernel(const float* __restrict__ x, int it) {
    extern __shared__ float smem[];
    float* Cs  = smem;
    float* c2s = Cs + 64 * KB;
    float* Xt  = c2s + KB;
    float* Xr  = Xt + 64 * XTS;
    float* Ms  = Xr + PB * XRS;
    float* x2s = Ms + PB * MSS;
    int* flagp = (int*)(x2s + PB);

    const int tid = threadIdx.x;
    const int ty = tid >> 4, tx = tid & 15;
    const int ck0 = ty * 8, p0 = tx * 8, dq = tx * 4;
    const int kb = blockIdx.y * KB;
    const int ploc = tid & 127, d0 = (tid >> 7) * 32;
    const float* cin = &g_c[it & 1][0][0];

    for (int e = tid; e < KB * DIM; e += 256) {
        int ck = e & (KB - 1), d = e >> 7;
        Cs[d * KB + ck] = cin[(size_t)(kb + ck) * DIM + d];
    }
    __syncthreads();
    if (tid < KB) {
        float s = 0.f;
#pragma unroll
        for (int d = 0; d < DIM; d++) { float c = Cs[d * KB + tid]; s = fmaf(c, c, s); }
        c2s[tid] = s;
    }
    __syncthreads();

    u64p c2d[8];
#pragma unroll
    for (int i = 0; i < 8; i++) { float v = c2s[ck0 + i]; PK2(c2d[i], v, v); }
    u64p neg2; { float m2 = -2.0f; PK2(neg2, m2, m2); }

    u64p acc2[4][4];
#pragma unroll
    for (int i = 0; i < 4; i++)
#pragma unroll
        for (int j = 0; j < 4; j++) acc2[i][j] = 0ull;
    int cnti[8] = {0, 0, 0, 0, 0, 0, 0, 0};

    float4 pf[8];
    float pfx2 = 0.f;
    {
        const int tb = blockIdx.x * PB;
        bool valid = (tb + ploc) < NPTS;
        const float4* src = (const float4*)(x + (size_t)(tb + ploc) * DIM + d0);
#pragma unroll
        for (int k = 0; k < 8; k++)
            pf[k] = valid ? src[k] : make_float4(0.f, 0.f, 0.f, 0.f);
        if (tid < PB) pfx2 = ((tb + tid) < NPTS) ? g_x2[tb + tid] : -1e30f;
    }

    for (int t = blockIdx.x; t < NT128; t += GXI) {
        __syncthreads();
        if (tid == 0) *flagp = 0;
        {
#pragma unroll
            for (int k = 0; k < 8; k++) {
                float4 v = pf[k];
                *(float4*)(Xr + ploc * XRS + d0 + 4 * k) = v;
                Xt[(d0 + 4 * k + 0) * XTS + ploc] = v.x;
                Xt[(d0 + 4 * k + 1) * XTS + ploc] = v.y;
                Xt[(d0 + 4 * k + 2) * XTS + ploc] = v.z;
                Xt[(d0 + 4 * k + 3) * XTS + ploc] = v.w;
            }
            if (tid < PB) x2s[tid] = pfx2;
        }
        __syncthreads();

        const int tn = t + GXI;
        if (tn < NT128) {
            const int tbn = tn * PB;
            bool valid = (tbn + ploc) < NPTS;
            const float4* src = (const float4*)(x + (size_t)(tbn + ploc) * DIM + d0);
#pragma unroll
            for (int k = 0; k < 8; k++)
                pf[k] = valid ? src[k] : make_float4(0.f, 0.f, 0.f, 0.f);
            if (tid < PB) pfx2 = ((tbn + tid) < NPTS) ? g_x2[tbn + tid] : -1e30f;
        }

        u64p S2[8][4];
#pragma unroll
        for (int i = 0; i < 8; i++)
#pragma unroll
            for (int j = 0; j < 4; j++) S2[i][j] = 0ull;

#pragma unroll 8
        for (int dd = 0; dd < DIM; dd++) {
            float4 ca = *(const float4*)(Cs + dd * KB + ck0);
            float4 cb = *(const float4*)(Cs + dd * KB + ck0 + 4);
            float4 xa = *(const float4*)(Xt + dd * XTS + p0);
            float4 xb = *(const float4*)(Xt + dd * XTS + p0 + 4);
            u64p xp[4];
            PK2(xp[0], xa.x, xa.y); PK2(xp[1], xa.z, xa.w);
            PK2(xp[2], xb.x, xb.y); PK2(xp[3], xb.z, xb.w);
            float cv[8] = {ca.x, ca.y, ca.z, ca.w, cb.x, cb.y, cb.z, cb.w};
#pragma unroll
            for (int i = 0; i < 8; i++) {
                u64p cd; PK2(cd, cv[i], cv[i]);
#pragma unroll
                for (int j = 0; j < 4; j++) FMA2(S2[i][j], cd, xp[j], S2[i][j]);
            }
        }

        unsigned long long bits = 0ull;
#pragma unroll
        for (int jp = 0; jp < 4; jp++) {
            u64p x2p; PK2(x2p, x2s[p0 + 2 * jp], x2s[p0 + 2 * jp + 1]);
#pragma unroll
            for (int i = 0; i < 8; i++) {
                u64p tsum; ADD2(tsum, c2d[i], x2p);
                u64p d2;   FMA2(d2, neg2, S2[i][jp], tsum);
                float dlo, dhi; UPK2(dlo, dhi, d2);
                if (!(dlo < BW2)) bits |= 1ull << (i * 8 + 2 * jp);
                if (!(dhi < BW2)) bits |= 1ull << (i * 8 + 2 * jp + 1);
            }
        }
#pragma unroll
        for (int i = 0; i < 8; i++)
            cnti[i] += __popc((unsigned)((bits >> (i * 8)) & 0xFFull));

        unsigned bal = __ballot_sync(0xffffffffu, bits != 0ull);
        if (bal != 0u && (tid & 31) == 0) atomicOr(flagp, 1);
        __syncthreads();

        if (*flagp) {
            const int sw = tx & 7;
            const int colA = 4 * ((2 * ty) ^ sw);
            const int colB = 4 * ((2 * ty + 1) ^ sw);
#pragma unroll
            for (int jp = 0; jp < 4; jp++) {
                int j0 = 2 * jp, j1 = 2 * jp + 1;
                float4 a0, b0, a1, b1;
                a0.x = (float)((bits >> (0 * 8 + j0)) & 1ull);
                a0.y = (float)((bits >> (1 * 8 + j0)) & 1ull);
                a0.z = (float)((bits >> (2 * 8 + j0)) & 1ull);
                a0.w = (float)((bits >> (3 * 8 + j0)) & 1ull);
                b0.x = (float)((bits >> (4 * 8 + j0)) & 1ull);
                b0.y = (float)((bits >> (5 * 8 + j0)) & 1ull);
                b0.z = (float)((bits >> (6 * 8 + j0)) & 1ull);
                b0.w = (float)((bits >> (7 * 8 + j0)) & 1ull);
                a1.x = (float)((bits >> (0 * 8 + j1)) & 1ull);
                a1.y = (float)((bits >> (1 * 8 + j1)) & 1ull);
                a1.z = (float)((bits >> (2 * 8 + j1)) & 1ull);
                a1.w = (float)((bits >> (3 * 8 + j1)) & 1ull);
                b1.x = (float)((bits >> (4 * 8 + j1)) & 1ull);
                b1.y = (float)((bits >> (5 * 8 + j1)) & 1ull);
                b1.z = (float)((bits >> (6 * 8 + j1)) & 1ull);
                b1.w = (float)((bits >> (7 * 8 + j1)) & 1ull);
                int pA = p0 + j0, pB = p0 + j1;
                *(float4*)(Ms + pA * MSS + colA) = a0;
                *(float4*)(Ms + pA * MSS + colB) = b0;
                *(float4*)(Ms + pB * MSS + colA) = a1;
                *(float4*)(Ms + pB * MSS + colB) = b1;
            }
            __syncthreads();

#pragma unroll 4
            for (int p = 0; p < PB; p++) {
                const int sw2 = (p >> 3) & 7;
                float4 ma = *(const float4*)(Ms + p * MSS + 4 * ((2 * ty) ^ sw2));
                float4 mb = *(const float4*)(Ms + p * MSS + 4 * ((2 * ty + 1) ^ sw2));
                float4 xv = *(const float4*)(Xr + p * XRS + dq);
                u64p mp[4];
                PK2(mp[0], ma.x, ma.y); PK2(mp[1], ma.z, ma.w);
                PK2(mp[2], mb.x, mb.y); PK2(mp[3], mb.z, mb.w);
                u64p xd[4];
                PK2(xd[0], xv.x, xv.x); PK2(xd[1], xv.y, xv.y);
                PK2(xd[2], xv.z, xv.z); PK2(xd[3], xv.w, xv.w);
#pragma unroll
                for (int i2 = 0; i2 < 4; i2++)
#pragma unroll
                    for (int j = 0; j < 4; j++) FMA2(acc2[i2][j], mp[i2], xd[j], acc2[i2][j]);
            }
        }
    }

#pragma unroll
    for (int i2 = 0; i2 < 4; i2++)
#pragma unroll
        for (int j = 0; j < 4; j++) {
            float alo, ahi; UPK2(alo, ahi, acc2[i2][j]);
            atomicAdd(&g_acc[kb + ck0 + 2 * i2 + 0][dq + j], alo);
            atomicAdd(&g_acc[kb + ck0 + 2 * i2 + 1][dq + j], ahi);
        }
#pragma unroll
    for (int i = 0; i < 8; i++) {
        float v = (float)cnti[i];
#pragma unroll
        for (int off = 8; off > 0; off >>= 1)
            v += __shfl_down_sync(0xffffffffu, v, off, 16);
        if (tx == 0) atomicAdd(&g_cnt[kb + ck0 + i], v);
    }
}

// ------------------------------------------- persistent sparse iterations 1..9
// Round-7 structure (2 grid-syncs/iter, distributed update, shared buffers)
// + fixed-point early exit via per-iteration change flags.

static __device__ __forceinline__ void grid_sync() {
    __threadfence();
    __syncthreads();
    if (threadIdx.x == 0) {
        unsigned gen = g_bargen;
        if (atomicAdd(&g_barcnt, 1u) == SPB - 1) {
            g_barcnt = 0;
            __threadfence();
            g_bargen = gen + 1;
        } else {
            while (g_bargen == gen) { __nanosleep(32); }
        }
    }
    __syncthreads();
}

__global__ void __launch_bounds__(256) sparse_all(const float* __restrict__ x) {
    __shared__ float red[KC];
    const int tid = threadIdx.x;
    const int gtid = blockIdx.x * 256 + tid;
    const int stride = SPB * 256;

    for (int it = 1; it < ITERS; it++) {
        const float* cc = &g_c[it & 1][0][0];

        // block-local cmax (identical across blocks)
        {
            const float4* cr = (const float4*)(cc + (size_t)tid * DIM);
            float c2 = 0.f;
#pragma unroll
            for (int q = 0; q < 16; q++) {
                float4 v = cr[q];
                c2 = fmaf(v.x, v.x, c2); c2 = fmaf(v.y, v.y, c2);
                c2 = fmaf(v.z, v.z, c2); c2 = fmaf(v.w, v.w, c2);
            }
            red[tid] = c2;
            __syncthreads();
            for (int s = 128; s > 0; s >>= 1) {
                if (tid < s) red[tid] = fmaxf(red[tid], red[tid + s]);
                __syncthreads();
            }
        }
        const float cmax = sqrtf(red[0]) + 1e-3f;
        __syncthreads();
        float tthr = 12.0f - cmax - 1e-3f;
        const float thr2 = (tthr > 0.f) ? tthr * tthr : -1.0f;

        // candidate scan + exact exception check; record tileflags every
        // iteration (union = conservative superset; at the exit iteration the
        // centers equal c9 bitwise, so the c9-candidate set is covered)
        for (int n = gtid; n < NPTS; n += stride) {
            const float x2 = g_x2[n];
            if (x2 < thr2) continue;
            g_tileflag[n >> 6] = 1;

            float xv[DIM];
            const float4* xr = (const float4*)(x + (size_t)n * DIM);
#pragma unroll
            for (int q = 0; q < 16; q++) {
                float4 v = xr[q];
                xv[4 * q + 0] = v.x; xv[4 * q + 1] = v.y;
                xv[4 * q + 2] = v.z; xv[4 * q + 3] = v.w;
            }
            for (int k = 0; k < KC; k++) {
                const float4* cr = (const float4*)(cc + (size_t)k * DIM);
                float dot = 0.f, c2 = 0.f;
#pragma unroll
                for (int q = 0; q < 16; q++) {
                    float4 cv = cr[q];
                    dot = fmaf(cv.x, xv[4 * q + 0], dot);
                    dot = fmaf(cv.y, xv[4 * q + 1], dot);
                    dot = fmaf(cv.z, xv[4 * q + 2], dot);
                    dot = fmaf(cv.w, xv[4 * q + 3], dot);
                    c2 = fmaf(cv.x, cv.x, c2); c2 = fmaf(cv.y, cv.y, c2);
                    c2 = fmaf(cv.z, cv.z, c2); c2 = fmaf(cv.w, cv.w, c2);
                }
                float d2 = c2 + x2 - 2.f * dot;
                if (!(d2 < BW2)) {
                    atomicAdd(&g_cnt[k], 1.0f);
#pragma unroll
                    for (int d = 0; d < DIM; d++) atomicAdd(&g_acc[k][d], xv[d]);
                }
            }
        }

        grid_sync();   // exception atomics visible

        // distributed update + per-block change detection
        int diff = 0;
        {
            int k = -1, d = tid & 63;
            if (tid < 64) k = blockIdx.x;
            else if (tid < 128) { int kk = blockIdx.x + SPB; if (kk < KC) k = kk; }
            if (k >= 0) {
                double cnt = (double)NPTS - (double)g_cnt[k];
                double v = (g_sumx[d] - (double)g_acc[k][d]) / cnt;
                float nf = (float)v;
                if (__float_as_uint(nf) != __float_as_uint(g_c[it & 1][k][d])) diff = 1;
                g_c[(it + 1) & 1][k][d] = nf;
                g_acc[k][d] = 0.f;
            }
        }
        if (__syncthreads_or(diff) && tid == 0) atomicOr(&g_chgA[it], 1);
        if (tid == 0) {
            g_cnt[blockIdx.x] = 0.f;
            int kk = blockIdx.x + SPB;
            if (kk < KC) g_cnt[kk] = 0.f;
        }

        grid_sync();   // updates + resets + change flags visible

        if (g_chgA[it] == 0) break;   // fixed point -> skip remaining iterations
    }
}

// ------------------------------------------- final masked argmin, f32x2
// Round-7 version (part of the measured-best 899us config): KB=128, (256,2).

__global__ void __launch_bounds__(256, 2) final_kernel(const float* __restrict__ x) {
    extern __shared__ float sm[];
    float* Ct   = sm;                 // [64][128] c10 transposed
    float* c210 = Ct + 64 * KB;       // [128]
    float* Xt   = c210 + KB;          // [64][132]
    float* x2s  = Xt + 64 * XTS;      // [128]

    const int tid = threadIdx.x;
    const int ty = tid >> 4, tx = tid & 15;
    const int ck0 = ty * 8, p0 = tx * 8;
    const int kb = blockIdx.y * KB;

    for (int e = tid; e < KB * DIM; e += 256) {
        int ck = e & (KB - 1), d = e >> 7;
        Ct[d * KB + ck] = g_c[0][kb + ck][d];
    }
    __syncthreads();
    if (tid < KB) {
        float s = 0.f;
#pragma unroll
        for (int d = 0; d < DIM; d++) { float a = Ct[d * KB + tid]; s = fmaf(a, a, s); }
        c210[tid] = s;
    }
    __syncthreads();

    unsigned long long best[8];
#pragma unroll
    for (int i = 0; i < 8; i++) best[i] = ~0ull;

    for (int t = blockIdx.x; t < NT128; t += GXF) {
        const int tb = t * PB;
        __syncthreads();
        {
            int ploc = tid & 127, d0 = (tid >> 7) * 32;
            bool valid = (tb + ploc) < NPTS;
            const float4* src = (const float4*)(x + (size_t)(tb + ploc) * DIM + d0);
#pragma unroll
            for (int k = 0; k < 8; k++) {
                float4 v = valid ? src[k] : make_float4(0.f, 0.f, 0.f, 0.f);
                Xt[(d0 + 4 * k + 0) * XTS + ploc] = v.x;
                Xt[(d0 + 4 * k + 1) * XTS + ploc] = v.y;
                Xt[(d0 + 4 * k + 2) * XTS + ploc] = v.z;
                Xt[(d0 + 4 * k + 3) * XTS + ploc] = v.w;
            }
            if (tid < PB) x2s[tid] = ((tb + tid) < NPTS) ? g_x2[tb + tid] : 0.f;
        }
        __syncthreads();

        u64p S2[8][4];
#pragma unroll
        for (int i = 0; i < 8; i++)
#pragma unroll
            for (int j = 0; j < 4; j++) S2[i][j] = 0ull;

#pragma unroll 8
        for (int dd = 0; dd < DIM; dd++) {
            float4 ca = *(const float4*)(Ct + dd * KB + ck0);
            float4 cb = *(const float4*)(Ct + dd * KB + ck0 + 4);
            float4 xa = *(const float4*)(Xt + dd * XTS + p0);
            float4 xb = *(const float4*)(Xt + dd * XTS + p0 + 4);
            u64p xp[4];
            PK2(xp[0], xa.x, xa.y); PK2(xp[1], xa.z, xa.w);
            PK2(xp[2], xb.x, xb.y); PK2(xp[3], xb.z, xb.w);
            float cv[8] = {ca.x, ca.y, ca.z, ca.w, cb.x, cb.y, cb.z, cb.w};
#pragma unroll
            for (int i = 0; i < 8; i++) {
                u64p cd; PK2(cd, cv[i], cv[i]);
#pragma unroll
                for (int j = 0; j < 4; j++) FMA2(S2[i][j], cd, xp[j], S2[i][j]);
            }
        }

        const int flagged = g_tileflag[2 * t] |
                            ((2 * t + 1 < NT64) ? g_tileflag[2 * t + 1] : 0);

#pragma unroll
        for (int jp = 0; jp < 4; jp++) {
            const int pA = p0 + 2 * jp, pB = pA + 1;
            const float xa2 = x2s[pA], xb2 = x2s[pB];
            const unsigned ia = (unsigned)(tb + pA), ib = (unsigned)(tb + pB);
#pragma unroll
            for (int i = 0; i < 8; i++) {
                float dlo, dhi; UPK2(dlo, dhi, S2[i][jp]);
                const float c2v = c210[ck0 + i];
                bool oka = true, okb = true;
                if (flagged) {
                    const float* c9r = &g_c[1][kb + ck0 + i][0];
                    float d9a = 0.f, d9b = 0.f, c29v = 0.f;
                    for (int dd = 0; dd < DIM; dd++) {
                        float cv9 = c9r[dd];
                        d9a = fmaf(cv9, Xt[dd * XTS + pA], d9a);
                        d9b = fmaf(cv9, Xt[dd * XTS + pB], d9b);
                        c29v = fmaf(cv9, cv9, c29v);
                    }
                    oka = fmaf(-2.f, d9a, c29v + xa2) < BW2;
                    okb = fmaf(-2.f, d9b, c29v + xb2) < BW2;
                }
                if (oka && ia < NPTS) {
                    float d2 = fmaxf(fmaf(-2.f, dlo, c2v + xa2), 0.f);
                    unsigned long long key =
                        ((unsigned long long)__float_as_uint(d2) << 32) | ia;
                    if (key < best[i]) best[i] = key;
                }
                if (okb && ib < NPTS) {
                    float d2 = fmaxf(fmaf(-2.f, dhi, c2v + xb2), 0.f);
                    unsigned long long key =
                        ((unsigned long long)__float_as_uint(d2) << 32) | ib;
                    if (key < best[i]) best[i] = key;
                }
            }
        }
    }

#pragma unroll
    for (int i = 0; i < 8; i++) {
        unsigned long long v = best[i];
#pragma unroll
        for (int off = 8; off > 0; off >>= 1) {
            unsigned long long o = __shfl_down_sync(0xffffffffu, v, off, 16);
            if (o < v) v = o;
        }
        if (tx == 0) atomicMin(&g_best[kb + ck0 + i], v);
    }
}

// ---------------------------------------------------------------- epilogue

__global__ void zero_out(float* out, int n) {
    int i = blockIdx.x * blockDim.x + threadIdx.x;
    if (i < n) out[i] = 0.f;
}

__global__ void finish_kernel(float* __restrict__ out, const float* __restrict__ x,
                              int out_size) {
    int k = blockIdx.x, d = threadIdx.x;
    if (out_size >= KC * DIM)
        out[k * DIM + d] = g_c[0][k][d];
    unsigned long long b = g_best[k];
    unsigned idx = (b == ~0ull) ? 0u : (unsigned)(b & 0xffffffffu);
    if (out_size >= 2 * KC * DIM)
        out[KC * DIM + k * DIM + d] = x[(size_t)idx * DIM + d];
    if (d == 0 && out_size >= 2 * KC * DIM + KC)
        out[2 * KC * DIM + k] = (float)idx;
}

// ---------------------------------------------------------------- launcher

extern "C" void kernel_launch(void* const* d_in, const int* in_sizes, int n_in,
                              void* d_out, int out_size) {
    const float* x = (const float*)d_in[0];
    const void* seed = d_in[1];
    float* out = (float*)d_out;
    (void)in_sizes; (void)n_in;

    const size_t iterSmem = (size_t)(64 * KB + KB + 64 * XTS + PB * XRS + PB * MSS + PB + 16)
                            * sizeof(float);
    const size_t finalSmem = (size_t)(64 * KB + KB + 64 * XTS + PB) * sizeof(float);
    cudaFuncSetAttribute(iter_kernel,  cudaFuncAttributeMaxDynamicSharedMemorySize, (int)iterSmem);
    cudaFuncSetAttribute(final_kernel, cudaFuncAttributeMaxDynamicSharedMemorySize, (int)finalSmem);

    detect_kernel<<<1, 128>>>(seed);
    x2_kernel<<<(NPTS + 255) / 256, 256>>>(x);
    seed_kernel<<<KC, DIM>>>(x, seed);

    iter_kernel<<<dim3(GXI, KC / KB), 256, iterSmem>>>(x, 0);
    update_kernel<<<KC, DIM>>>(0);

    sparse_all<<<SPB, 256>>>(x);

    final_kernel<<<dim3(GXF, KC / KB), 256, finalSmem>>>(x);

    if (out_size > 0)
        zero_out<<<(out_size + 255) / 256, 256>>>(out, out_size);
    finish_kernel<<<KC, DIM>>>(out, x, out_size);
}

// round 12
// speedup vs baseline: 1.7314x; 1.4515x over previous
#include <cuda_runtime.h>
#include <cuda_bf16.h>
#include <stdint.h>

#define NPTS 200000
#define DIM 64
#define KC 256
#define BW2 144.0f
#define ITERS 10

#define KB 128
#define PB 128
#define NT128 1563
#define GXI 74
#define GXF 148
#define XTS 132
#define XRS 68
#define MSS 132
#define NT64 3125
#define SPB 148
#define CCAP 4096

typedef unsigned long long u64p;
#define PK2(d, lo, hi) asm("mov.b64 %0, {%1, %2};" : "=l"(d) : "f"(lo), "f"(hi))
#define UPK2(lo, hi, s) asm("mov.b64 {%0, %1}, %2;" : "=f"(lo), "=f"(hi) : "l"(s))
#define FMA2(d, a, b, c) asm("fma.rn.f32x2 %0, %1, %2, %3;" : "=l"(d) : "l"(a), "l"(b), "l"(c))
#define ADD2(d, a, b) asm("add.rn.f32x2 %0, %1, %2;" : "=l"(d) : "l"(a), "l"(b))

__device__ float g_c[2][KC][DIM];
__device__ float g_acc[KC][DIM];
__device__ float g_cnt[KC];
__device__ double g_sumx[DIM];
__device__ float g_x2[NPTS];
__device__ unsigned long long g_best[KC];
__device__ int g_seed64;
__device__ int g_tileflag[NT64];
__device__ int g_chgA[ITERS];
__device__ unsigned g_barcnt;
__device__ volatile unsigned g_bargen;
__device__ unsigned g_minx2bits;
__device__ int g_ncand;
__device__ int g_cand[CCAP];
__device__ int g_finaldone;

// ------------------------------------------------- prologue kernels

__global__ void detect_kernel(const void* __restrict__ seed) {
    __shared__ int bad;
    if (threadIdx.x == 0) {
        bad = 0;
        g_minx2bits = 0x7f7fffffu;   // FLT_MAX
        g_ncand = 0;
        g_finaldone = 0;
    }
    if (threadIdx.x < DIM) g_sumx[threadIdx.x] = 0.0;
    __syncthreads();
    unsigned long long v = ((const unsigned long long*)seed)[threadIdx.x];
    if (v >= (unsigned long long)NPTS) atomicOr(&bad, 1);
    __syncthreads();
    if (threadIdx.x == 0) g_seed64 = bad ? 0 : 1;
}

// x2 per point + fused column sum + global min(x2) + flag zeroing
__global__ void x2_kernel(const float* __restrict__ x) {
    __shared__ float wsum[8][DIM];
    const int tid = threadIdx.x;
    const int n = blockIdx.x * 256 + tid;
    const int lane = tid & 31, wid = tid >> 5;
    const bool valid = n < NPTS;
    const float4* r = (const float4*)(x + (size_t)n * DIM);

    float x2 = 0.f;
#pragma unroll
    for (int q = 0; q < 16; q++) {
        float4 v = valid ? r[q] : make_float4(0.f, 0.f, 0.f, 0.f);
        x2 = fmaf(v.x, v.x, x2); x2 = fmaf(v.y, v.y, x2);
        x2 = fmaf(v.z, v.z, x2); x2 = fmaf(v.w, v.w, x2);
#pragma unroll
        for (int off = 16; off > 0; off >>= 1) {
            v.x += __shfl_xor_sync(0xffffffffu, v.x, off);
            v.y += __shfl_xor_sync(0xffffffffu, v.y, off);
            v.z += __shfl_xor_sync(0xffffffffu, v.z, off);
            v.w += __shfl_xor_sync(0xffffffffu, v.w, off);
        }
        if (lane == 0) *(float4*)&wsum[wid][4 * q] = v;
    }
    if (valid) g_x2[n] = x2;
    if (n < NT64) g_tileflag[n] = 0;
    if (n < ITERS) g_chgA[n] = 0;
    {   // global min of x2 (uint-order == float-order for x2 >= 0)
        float m = valid ? x2 : 1e30f;
#pragma unroll
        for (int off = 16; off > 0; off >>= 1)
            m = fminf(m, __shfl_xor_sync(0xffffffffu, m, off));
        if (lane == 0) atomicMin(&g_minx2bits, __float_as_uint(m));
    }
    __syncthreads();
    if (tid < DIM) {
        float tot = 0.f;
#pragma unroll
        for (int w = 0; w < 8; w++) tot += wsum[w][tid];
        atomicAdd(&g_sumx[tid], (double)tot);
    }
}

__global__ void seed_kernel(const float* __restrict__ x, const void* __restrict__ seedraw) {
    int k = blockIdx.x, d = threadIdx.x;
    long long idx;
    if (g_seed64) idx = ((const long long*)seedraw)[k];
    else          idx = (long long)(((const int*)seedraw)[k]);
    g_c[0][k][d] = x[idx * DIM + d];
    g_acc[k][d] = 0.f;
    if (d == 0) { g_cnt[k] = 0.f; g_best[k] = ~0ull; }
}

__global__ void update_kernel(int it) {
    int k = blockIdx.x, d = threadIdx.x;
    double cnt = (double)NPTS - (double)g_cnt[k];
    double v = (g_sumx[d] - (double)g_acc[k][d]) / cnt;
    __syncthreads();
    g_c[(it + 1) & 1][k][d] = (float)v;
    g_acc[k][d] = 0.f;
    if (d == 0) g_cnt[k] = 0.f;
}

// ------------------------------------------- dense iteration (it=0)
// Software-pipelined (measured 376us).

__global__ void __launch_bounds__(256, 1) iter_kernel(const float* __restrict__ x, int it) {
    extern __shared__ float smem[];
    float* Cs  = smem;
    float* c2s = Cs + 64 * KB;
    float* Xt  = c2s + KB;
    float* Xr  = Xt + 64 * XTS;
    float* Ms  = Xr + PB * XRS;
    float* x2s = Ms + PB * MSS;
    int* flagp = (int*)(x2s + PB);

    const int tid = threadIdx.x;
    const int ty = tid >> 4, tx = tid & 15;
    const int ck0 = ty * 8, p0 = tx * 8, dq = tx * 4;
    const int kb = blockIdx.y * KB;
    const int ploc = tid & 127, d0 = (tid >> 7) * 32;
    const float* cin = &g_c[it & 1][0][0];

    for (int e = tid; e < KB * DIM; e += 256) {
        int ck = e & (KB - 1), d = e >> 7;
        Cs[d * KB + ck] = cin[(size_t)(kb + ck) * DIM + d];
    }
    __syncthreads();
    if (tid < KB) {
        float s = 0.f;
#pragma unroll
        for (int d = 0; d < DIM; d++) { float c = Cs[d * KB + tid]; s = fmaf(c, c, s); }
        c2s[tid] = s;
    }
    __syncthreads();

    u64p c2d[8];
#pragma unroll
    for (int i = 0; i < 8; i++) { float v = c2s[ck0 + i]; PK2(c2d[i], v, v); }
    u64p neg2; { float m2 = -2.0f; PK2(neg2, m2, m2); }

    u64p acc2[4][4];
#pragma unroll
    for (int i = 0; i < 4; i++)
#pragma unroll
        for (int j = 0; j < 4; j++) acc2[i][j] = 0ull;
    int cnti[8] = {0, 0, 0, 0, 0, 0, 0, 0};

    float4 pf[8];
    float pfx2 = 0.f;
    {
        const int tb = blockIdx.x * PB;
        bool valid = (tb + ploc) < NPTS;
        const float4* src = (const float4*)(x + (size_t)(tb + ploc) * DIM + d0);
#pragma unroll
        for (int k = 0; k < 8; k++)
            pf[k] = valid ? src[k] : make_float4(0.f, 0.f, 0.f, 0.f);
        if (tid < PB) pfx2 = ((tb + tid) < NPTS) ? g_x2[tb + tid] : -1e30f;
    }

    for (int t = blockIdx.x; t < NT128; t += GXI) {
        __syncthreads();
        if (tid == 0) *flagp = 0;
        {
#pragma unroll
            for (int k = 0; k < 8; k++) {
                float4 v = pf[k];
                *(float4*)(Xr + ploc * XRS + d0 + 4 * k) = v;
                Xt[(d0 + 4 * k + 0) * XTS + ploc] = v.x;
                Xt[(d0 + 4 * k + 1) * XTS + ploc] = v.y;
                Xt[(d0 + 4 * k + 2) * XTS + ploc] = v.z;
                Xt[(d0 + 4 * k + 3) * XTS + ploc] = v.w;
            }
            if (tid < PB) x2s[tid] = pfx2;
        }
        __syncthreads();

        const int tn = t + GXI;
        if (tn < NT128) {
            const int tbn = tn * PB;
            bool valid = (tbn + ploc) < NPTS;
            const float4* src = (const float4*)(x + (size_t)(tbn + ploc) * DIM + d0);
#pragma unroll
            for (int k = 0; k < 8; k++)
                pf[k] = valid ? src[k] : make_float4(0.f, 0.f, 0.f, 0.f);
            if (tid < PB) pfx2 = ((tbn + tid) < NPTS) ? g_x2[tbn + tid] : -1e30f;
        }

        u64p S2[8][4];
#pragma unroll
        for (int i = 0; i < 8; i++)
#pragma unroll
            for (int j = 0; j < 4; j++) S2[i][j] = 0ull;

#pragma unroll 8
        for (int dd = 0; dd < DIM; dd++) {
            float4 ca = *(const float4*)(Cs + dd * KB + ck0);
            float4 cb = *(const float4*)(Cs + dd * KB + ck0 + 4);
            float4 xa = *(const float4*)(Xt + dd * XTS + p0);
            float4 xb = *(const float4*)(Xt + dd * XTS + p0 + 4);
            u64p xp[4];
            PK2(xp[0], xa.x, xa.y); PK2(xp[1], xa.z, xa.w);
            PK2(xp[2], xb.x, xb.y); PK2(xp[3], xb.z, xb.w);
            float cv[8] = {ca.x, ca.y, ca.z, ca.w, cb.x, cb.y, cb.z, cb.w};
#pragma unroll
            for (int i = 0; i < 8; i++) {
                u64p cd; PK2(cd, cv[i], cv[i]);
#pragma unroll
                for (int j = 0; j < 4; j++) FMA2(S2[i][j], cd, xp[j], S2[i][j]);
            }
        }

        unsigned long long bits = 0ull;
#pragma unroll
        for (int jp = 0; jp < 4; jp++) {
            u64p x2p; PK2(x2p, x2s[p0 + 2 * jp], x2s[p0 + 2 * jp + 1]);
#pragma unroll
            for (int i = 0; i < 8; i++) {
                u64p tsum; ADD2(tsum, c2d[i], x2p);
                u64p d2;   FMA2(d2, neg2, S2[i][jp], tsum);
                float dlo, dhi; UPK2(dlo, dhi, d2);
                if (!(dlo < BW2)) bits |= 1ull << (i * 8 + 2 * jp);
                if (!(dhi < BW2)) bits |= 1ull << (i * 8 + 2 * jp + 1);
            }
        }
#pragma unroll
        for (int i = 0; i < 8; i++)
            cnti[i] += __popc((unsigned)((bits >> (i * 8)) & 0xFFull));

        unsigned bal = __ballot_sync(0xffffffffu, bits != 0ull);
        if (bal != 0u && (tid & 31) == 0) atomicOr(flagp, 1);
        __syncthreads();

        if (*flagp) {
            const int sw = tx & 7;
            const int colA = 4 * ((2 * ty) ^ sw);
            const int colB = 4 * ((2 * ty + 1) ^ sw);
#pragma unroll
            for (int jp = 0; jp < 4; jp++) {
                int j0 = 2 * jp, j1 = 2 * jp + 1;
                float4 a0, b0, a1, b1;
                a0.x = (float)((bits >> (0 * 8 + j0)) & 1ull);
                a0.y = (float)((bits >> (1 * 8 + j0)) & 1ull);
                a0.z = (float)((bits >> (2 * 8 + j0)) & 1ull);
                a0.w = (float)((bits >> (3 * 8 + j0)) & 1ull);
                b0.x = (float)((bits >> (4 * 8 + j0)) & 1ull);
                b0.y = (float)((bits >> (5 * 8 + j0)) & 1ull);
                b0.z = (float)((bits >> (6 * 8 + j0)) & 1ull);
                b0.w = (float)((bits >> (7 * 8 + j0)) & 1ull);
                a1.x = (float)((bits >> (0 * 8 + j1)) & 1ull);
                a1.y = (float)((bits >> (1 * 8 + j1)) & 1ull);
                a1.z = (float)((bits >> (2 * 8 + j1)) & 1ull);
                a1.w = (float)((bits >> (3 * 8 + j1)) & 1ull);
                b1.x = (float)((bits >> (4 * 8 + j1)) & 1ull);
                b1.y = (float)((bits >> (5 * 8 + j1)) & 1ull);
                b1.z = (float)((bits >> (6 * 8 + j1)) & 1ull);
                b1.w = (float)((bits >> (7 * 8 + j1)) & 1ull);
                int pA = p0 + j0, pB = p0 + j1;
                *(float4*)(Ms + pA * MSS + colA) = a0;
                *(float4*)(Ms + pA * MSS + colB) = b0;
                *(float4*)(Ms + pB * MSS + colA) = a1;
                *(float4*)(Ms + pB * MSS + colB) = b1;
            }
            __syncthreads();

#pragma unroll 4
            for (int p = 0; p < PB; p++) {
                const int sw2 = (p >> 3) & 7;
                float4 ma = *(const float4*)(Ms + p * MSS + 4 * ((2 * ty) ^ sw2));
                float4 mb = *(const float4*)(Ms + p * MSS + 4 * ((2 * ty + 1) ^ sw2));
                float4 xv = *(const float4*)(Xr + p * XRS + dq);
                u64p mp[4];
                PK2(mp[0], ma.x, ma.y); PK2(mp[1], ma.z, ma.w);
                PK2(mp[2], mb.x, mb.y); PK2(mp[3], mb.z, mb.w);
                u64p xd[4];
                PK2(xd[0], xv.x, xv.x); PK2(xd[1], xv.y, xv.y);
                PK2(xd[2], xv.z, xv.z); PK2(xd[3], xv.w, xv.w);
#pragma unroll
                for (int i2 = 0; i2 < 4; i2++)
#pragma unroll
                    for (int j = 0; j < 4; j++) FMA2(acc2[i2][j], mp[i2], xd[j], acc2[i2][j]);
            }
        }
    }

#pragma unroll
    for (int i2 = 0; i2 < 4; i2++)
#pragma unroll
        for (int j = 0; j < 4; j++) {
            float alo, ahi; UPK2(alo, ahi, acc2[i2][j]);
            atomicAdd(&g_acc[kb + ck0 + 2 * i2 + 0][dq + j], alo);
            atomicAdd(&g_acc[kb + ck0 + 2 * i2 + 1][dq + j], ahi);
        }
#pragma unroll
    for (int i = 0; i < 8; i++) {
        float v = (float)cnti[i];
#pragma unroll
        for (int off = 8; off > 0; off >>= 1)
            v += __shfl_down_sync(0xffffffffu, v, off, 16);
        if (tx == 0) atomicAdd(&g_cnt[kb + ck0 + i], v);
    }
}

// ------------------------------------------- persistent sparse iterations 1..9

static __device__ __forceinline__ void grid_sync() {
    __threadfence();
    __syncthreads();
    if (threadIdx.x == 0) {
        unsigned gen = g_bargen;
        if (atomicAdd(&g_barcnt, 1u) == SPB - 1) {
            g_barcnt = 0;
            __threadfence();
            g_bargen = gen + 1;
        } else {
            while (g_bargen == gen) { __nanosleep(32); }
        }
    }
    __syncthreads();
}

__global__ void __launch_bounds__(256) sparse_all(const float* __restrict__ x) {
    __shared__ float red[KC];
    const int tid = threadIdx.x;
    const int gtid = blockIdx.x * 256 + tid;
    const int stride = SPB * 256;

    for (int it = 1; it < ITERS; it++) {
        const float* cc = &g_c[it & 1][0][0];
        {
            const float4* cr = (const float4*)(cc + (size_t)tid * DIM);
            float c2 = 0.f;
#pragma unroll
            for (int q = 0; q < 16; q++) {
                float4 v = cr[q];
                c2 = fmaf(v.x, v.x, c2); c2 = fmaf(v.y, v.y, c2);
                c2 = fmaf(v.z, v.z, c2); c2 = fmaf(v.w, v.w, c2);
            }
            red[tid] = c2;
            __syncthreads();
            for (int s = 128; s > 0; s >>= 1) {
                if (tid < s) red[tid] = fmaxf(red[tid], red[tid + s]);
                __syncthreads();
            }
        }
        const float cmax = sqrtf(red[0]) + 1e-3f;
        __syncthreads();
        float tthr = 12.0f - cmax - 1e-3f;
        const float thr2 = (tthr > 0.f) ? tthr * tthr : -1.0f;

        for (int n = gtid; n < NPTS; n += stride) {
            const float x2 = g_x2[n];
            if (x2 < thr2) continue;
            g_tileflag[n >> 6] = 1;

            float xv[DIM];
            const float4* xr = (const float4*)(x + (size_t)n * DIM);
#pragma unroll
            for (int q = 0; q < 16; q++) {
                float4 v = xr[q];
                xv[4 * q + 0] = v.x; xv[4 * q + 1] = v.y;
                xv[4 * q + 2] = v.z; xv[4 * q + 3] = v.w;
            }
            for (int k = 0; k < KC; k++) {
                const float4* cr = (const float4*)(cc + (size_t)k * DIM);
                float dot = 0.f, c2 = 0.f;
#pragma unroll
                for (int q = 0; q < 16; q++) {
                    float4 cv = cr[q];
                    dot = fmaf(cv.x, xv[4 * q + 0], dot);
                    dot = fmaf(cv.y, xv[4 * q + 1], dot);
                    dot = fmaf(cv.z, xv[4 * q + 2], dot);
                    dot = fmaf(cv.w, xv[4 * q + 3], dot);
                    c2 = fmaf(cv.x, cv.x, c2); c2 = fmaf(cv.y, cv.y, c2);
                    c2 = fmaf(cv.z, cv.z, c2); c2 = fmaf(cv.w, cv.w, c2);
                }
                float d2 = c2 + x2 - 2.f * dot;
                if (!(d2 < BW2)) {
                    atomicAdd(&g_cnt[k], 1.0f);
#pragma unroll
                    for (int d = 0; d < DIM; d++) atomicAdd(&g_acc[k][d], xv[d]);
                }
            }
        }

        grid_sync();

        int diff = 0;
        {
            int k = -1, d = tid & 63;
            if (tid < 64) k = blockIdx.x;
            else if (tid < 128) { int kk = blockIdx.x + SPB; if (kk < KC) k = kk; }
            if (k >= 0) {
                double cnt = (double)NPTS - (double)g_cnt[k];
                double v = (g_sumx[d] - (double)g_acc[k][d]) / cnt;
                float nf = (float)v;
                if (__float_as_uint(nf) != __float_as_uint(g_c[it & 1][k][d])) diff = 1;
                g_c[(it + 1) & 1][k][d] = nf;
                g_acc[k][d] = 0.f;
            }
        }
        if (__syncthreads_or(diff) && tid == 0) atomicOr(&g_chgA[it], 1);
        if (tid == 0) {
            g_cnt[blockIdx.x] = 0.f;
            int kk = blockIdx.x + SPB;
            if (kk < KC) g_cnt[kk] = 0.f;
        }

        grid_sync();

        if (g_chgA[it] == 0) break;
    }
}

// ------------------------------------------- sparse final argmin
// Triangle bound: any x with |x| > |x*| + 2*cmax10 + eps cannot be any
// center's argmin. x* mask-truth proven via |x*| + cmax9 + eps < 12.
// Candidates get exact per-pair check (same ordering/keys as dense path).
// On any doubt -> g_finaldone stays 0 and the dense fallback runs.

__global__ void __launch_bounds__(256) final_sparse(const float* __restrict__ x) {
    __shared__ float redA[KC];
    __shared__ float redB[KC];
    __shared__ unsigned long long rmin[256];
    const int tid = threadIdx.x;
    const int gtid = blockIdx.x * 256 + tid;
    const int stride = SPB * 256;

    {   // cmax for c10 (g_c[0]) and c9 (g_c[1]) — identical across blocks
        const float4* ca = (const float4*)&g_c[0][tid][0];
        const float4* cb = (const float4*)&g_c[1][tid][0];
        float c2a = 0.f, c2b = 0.f;
#pragma unroll
        for (int q = 0; q < 16; q++) {
            float4 va = ca[q], vb = cb[q];
            c2a = fmaf(va.x, va.x, c2a); c2a = fmaf(va.y, va.y, c2a);
            c2a = fmaf(va.z, va.z, c2a); c2a = fmaf(va.w, va.w, c2a);
            c2b = fmaf(vb.x, vb.x, c2b); c2b = fmaf(vb.y, vb.y, c2b);
            c2b = fmaf(vb.z, vb.z, c2b); c2b = fmaf(vb.w, vb.w, c2b);
        }
        redA[tid] = c2a; redB[tid] = c2b;
        __syncthreads();
        for (int s = 128; s > 0; s >>= 1) {
            if (tid < s) {
                redA[tid] = fmaxf(redA[tid], redA[tid + s]);
                redB[tid] = fmaxf(redB[tid], redB[tid + s]);
            }
            __syncthreads();
        }
    }
    const float cmax10 = sqrtf(redA[0]) + 1e-3f;
    const float cmax9  = sqrtf(redB[0]) + 1e-3f;
    const float minx   = sqrtf(__uint_as_float(g_minx2bits));
    const float thr    = minx + 2.f * cmax10 + 0.05f;
    const float thr2   = thr * thr;
    const bool valid   = (minx + cmax9 + 0.05f < 12.0f);

    if (valid) {
        for (int n = gtid; n < NPTS; n += stride) {
            if (g_x2[n] <= thr2) {
                int pos = atomicAdd(&g_ncand, 1);
                if (pos < CCAP) g_cand[pos] = n;
            }
        }
    }
    grid_sync();
    const int ncand = g_ncand;
    if (!valid || ncand == 0 || ncand > CCAP) return;   // dense fallback handles

    for (int k = blockIdx.x; k < KC; k += SPB) {
        unsigned long long bk = ~0ull;
        for (int j = tid; j < ncand; j += 256) {
            const int n = g_cand[j];
            const float* xr = x + (size_t)n * DIM;
            const float x2 = g_x2[n];
            const float* c9r  = &g_c[1][k][0];
            const float* c10r = &g_c[0][k][0];
            float dot9 = 0.f, dot10 = 0.f, c29 = 0.f, c210 = 0.f;
            for (int d = 0; d < DIM; d++) {
                float xv = xr[d], v9 = c9r[d], v10 = c10r[d];
                dot9  = fmaf(v9,  xv, dot9);
                dot10 = fmaf(v10, xv, dot10);
                c29   = fmaf(v9,  v9,  c29);
                c210  = fmaf(v10, v10, c210);
            }
            float d9 = fmaf(-2.f, dot9, c29 + x2);
            if (d9 < BW2) {
                float d2 = fmaxf(fmaf(-2.f, dot10, c210 + x2), 0.f);
                unsigned long long key =
                    ((unsigned long long)__float_as_uint(d2) << 32) | (unsigned)n;
                if (key < bk) bk = key;
            }
        }
        rmin[tid] = bk;
        __syncthreads();
        for (int s = 128; s > 0; s >>= 1) {
            if (tid < s && rmin[tid + s] < rmin[tid]) rmin[tid] = rmin[tid + s];
            __syncthreads();
        }
        if (tid == 0 && rmin[0] != ~0ull) atomicMin(&g_best[k], rmin[0]);
        __syncthreads();
    }
    if (blockIdx.x == 0 && tid == 0) g_finaldone = 1;
}

// ------------------------------------------- dense final (fallback only)

__global__ void __launch_bounds__(256, 2) final_kernel(const float* __restrict__ x) {
    if (g_finaldone) return;
    extern __shared__ float sm[];
    float* Ct   = sm;
    float* c210 = Ct + 64 * KB;
    float* Xt   = c210 + KB;
    float* x2s  = Xt + 64 * XTS;

    const int tid = threadIdx.x;
    const int ty = tid >> 4, tx = tid & 15;
    const int ck0 = ty * 8, p0 = tx * 8;
    const int kb = blockIdx.y * KB;

    for (int e = tid; e < KB * DIM; e += 256) {
        int ck = e & (KB - 1), d = e >> 7;
        Ct[d * KB + ck] = g_c[0][kb + ck][d];
    }
    __syncthreads();
    if (tid < KB) {
        float s = 0.f;
#pragma unroll
        for (int d = 0; d < DIM; d++) { float a = Ct[d * KB + tid]; s = fmaf(a, a, s); }
        c210[tid] = s;
    }
    __syncthreads();

    unsigned long long best[8];
#pragma unroll
    for (int i = 0; i < 8; i++) best[i] = ~0ull;

    for (int t = blockIdx.x; t < NT128; t += GXF) {
        const int tb = t * PB;
        __syncthreads();
        {
            int ploc = tid & 127, d0 = (tid >> 7) * 32;
            bool valid = (tb + ploc) < NPTS;
            const float4* src = (const float4*)(x + (size_t)(tb + ploc) * DIM + d0);
#pragma unroll
            for (int k = 0; k < 8; k++) {
                float4 v = valid ? src[k] : make_float4(0.f, 0.f, 0.f, 0.f);
                Xt[(d0 + 4 * k + 0) * XTS + ploc] = v.x;
                Xt[(d0 + 4 * k + 1) * XTS + ploc] = v.y;
                Xt[(d0 + 4 * k + 2) * XTS + ploc] = v.z;
                Xt[(d0 + 4 * k + 3) * XTS + ploc] = v.w;
            }
            if (tid < PB) x2s[tid] = ((tb + tid) < NPTS) ? g_x2[tb + tid] : 0.f;
        }
        __syncthreads();

        u64p S2[8][4];
#pragma unroll
        for (int i = 0; i < 8; i++)
#pragma unroll
            for (int j = 0; j < 4; j++) S2[i][j] = 0ull;

#pragma unroll 8
        for (int dd = 0; dd < DIM; dd++) {
            float4 ca = *(const float4*)(Ct + dd * KB + ck0);
            float4 cb = *(const float4*)(Ct + dd * KB + ck0 + 4);
            float4 xa = *(const float4*)(Xt + dd * XTS + p0);
            float4 xb = *(const float4*)(Xt + dd * XTS + p0 + 4);
            u64p xp[4];
            PK2(xp[0], xa.x, xa.y); PK2(xp[1], xa.z, xa.w);
            PK2(xp[2], xb.x, xb.y); PK2(xp[3], xb.z, xb.w);
            float cv[8] = {ca.x, ca.y, ca.z, ca.w, cb.x, cb.y, cb.z, cb.w};
#pragma unroll
            for (int i = 0; i < 8; i++) {
                u64p cd; PK2(cd, cv[i], cv[i]);
#pragma unroll
                for (int j = 0; j < 4; j++) FMA2(S2[i][j], cd, xp[j], S2[i][j]);
            }
        }

        const int flagged = g_tileflag[2 * t] |
                            ((2 * t + 1 < NT64) ? g_tileflag[2 * t + 1] : 0);

#pragma unroll
        for (int jp = 0; jp < 4; jp++) {
            const int pA = p0 + 2 * jp, pB = pA + 1;
            const float xa2 = x2s[pA], xb2 = x2s[pB];
            const unsigned ia = (unsigned)(tb + pA), ib = (unsigned)(tb + pB);
#pragma unroll
            for (int i = 0; i < 8; i++) {
                float dlo, dhi; UPK2(dlo, dhi, S2[i][jp]);
                const float c2v = c210[ck0 + i];
                bool oka = true, okb = true;
                if (flagged) {
                    const float* c9r = &g_c[1][kb + ck0 + i][0];
                    float d9a = 0.f, d9b = 0.f, c29v = 0.f;
                    for (int dd = 0; dd < DIM; dd++) {
                        float cv9 = c9r[dd];
                        d9a = fmaf(cv9, Xt[dd * XTS + pA], d9a);
                        d9b = fmaf(cv9, Xt[dd * XTS + pB], d9b);
                        c29v = fmaf(cv9, cv9, c29v);
                    }
                    oka = fmaf(-2.f, d9a, c29v + xa2) < BW2;
                    okb = fmaf(-2.f, d9b, c29v + xb2) < BW2;
                }
                if (oka && ia < NPTS) {
                    float d2 = fmaxf(fmaf(-2.f, dlo, c2v + xa2), 0.f);
                    unsigned long long key =
                        ((unsigned long long)__float_as_uint(d2) << 32) | ia;
                    if (key < best[i]) best[i] = key;
                }
                if (okb && ib < NPTS) {
                    float d2 = fmaxf(fmaf(-2.f, dhi, c2v + xb2), 0.f);
                    unsigned long long key =
                        ((unsigned long long)__float_as_uint(d2) << 32) | ib;
                    if (key < best[i]) best[i] = key;
                }
            }
        }
    }

#pragma unroll
    for (int i = 0; i < 8; i++) {
        unsigned long long v = best[i];
#pragma unroll
        for (int off = 8; off > 0; off >>= 1) {
            unsigned long long o = __shfl_down_sync(0xffffffffu, v, off, 16);
            if (o < v) v = o;
        }
        if (tx == 0) atomicMin(&g_best[kb + ck0 + i], v);
    }
}

// ---------------------------------------------------------------- epilogue

__global__ void zero_out(float* out, int n) {
    int i = blockIdx.x * blockDim.x + threadIdx.x;
    if (i < n) out[i] = 0.f;
}

__global__ void finish_kernel(float* __restrict__ out, const float* __restrict__ x,
                              int out_size) {
    int k = blockIdx.x, d = threadIdx.x;
    if (out_size >= KC * DIM)
        out[k * DIM + d] = g_c[0][k][d];
    unsigned long long b = g_best[k];
    unsigned idx = (b == ~0ull) ? 0u : (unsigned)(b & 0xffffffffu);
    if (out_size >= 2 * KC * DIM)
        out[KC * DIM + k * DIM + d] = x[(size_t)idx * DIM + d];
    if (d == 0 && out_size >= 2 * KC * DIM + KC)
        out[2 * KC * DIM + k] = (float)idx;
}

// ---------------------------------------------------------------- launcher

extern "C" void kernel_launch(void* const* d_in, const int* in_sizes, int n_in,
                              void* d_out, int out_size) {
    const float* x = (const float*)d_in[0];
    const void* seed = d_in[1];
    float* out = (float*)d_out;
    (void)in_sizes; (void)n_in;

    const size_t iterSmem = (size_t)(64 * KB + KB + 64 * XTS + PB * XRS + PB * MSS + PB + 16)
                            * sizeof(float);
    const size_t finalSmem = (size_t)(64 * KB + KB + 64 * XTS + PB) * sizeof(float);
    cudaFuncSetAttribute(iter_kernel,  cudaFuncAttributeMaxDynamicSharedMemorySize, (int)iterSmem);
    cudaFuncSetAttribute(final_kernel, cudaFuncAttributeMaxDynamicSharedMemorySize, (int)finalSmem);

    detect_kernel<<<1, 128>>>(seed);
    x2_kernel<<<(NPTS + 255) / 256, 256>>>(x);
    seed_kernel<<<KC, DIM>>>(x, seed);

    iter_kernel<<<dim3(GXI, KC / KB), 256, iterSmem>>>(x, 0);
    update_kernel<<<KC, DIM>>>(0);

    sparse_all<<<SPB, 256>>>(x);

    final_sparse<<<SPB, 256>>>(x);
    final_kernel<<<dim3(GXF, KC / KB), 256, finalSmem>>>(x);

    if (out_size > 0)
        zero_out<<<(out_size + 255) / 256, 256>>>(out, out_size);
    finish_kernel<<<KC, DIM>>>(out, x, out_size);
}

// round 13
// speedup vs baseline: 2.7802x; 1.6057x over previous
#include <cuda_runtime.h>
#include <cuda_bf16.h>
#include <stdint.h>

#define NPTS 200000
#define DIM 64
#define KC 256
#define BW2 144.0f
#define ITERS 10

#define KB 128
#define PB 128
#define NT128 1563
#define GXI 74
#define GXF 148
#define XTS 132
#define XRS 68
#define MSS 132
#define NT64 3125
#define SPB 148
#define CCAP 4096

typedef unsigned long long u64p;
#define PK2(d, lo, hi) asm("mov.b64 %0, {%1, %2};" : "=l"(d) : "f"(lo), "f"(hi))
#define UPK2(lo, hi, s) asm("mov.b64 {%0, %1}, %2;" : "=f"(lo), "=f"(hi) : "l"(s))
#define FMA2(d, a, b, c) asm("fma.rn.f32x2 %0, %1, %2, %3;" : "=l"(d) : "l"(a), "l"(b), "l"(c))
#define ADD2(d, a, b) asm("add.rn.f32x2 %0, %1, %2;" : "=l"(d) : "l"(a), "l"(b))

__device__ float g_c[2][KC][DIM];
__device__ float g_acc[KC][DIM];
__device__ float g_cnt[KC];
__device__ double g_sumx[DIM];
__device__ float g_x2[NPTS];
__device__ unsigned long long g_best[KC];
__device__ int g_seed64;
__device__ int g_tileflag[NT64];
__device__ int g_chgA[ITERS];
__device__ unsigned g_barcnt;
__device__ volatile unsigned g_bargen;
__device__ unsigned g_minx2bits;
__device__ int g_ncand;
__device__ int g_cand[CCAP];
__device__ int g_finaldone;

// ------------------------------------------------- prologue kernels

__global__ void detect_kernel(const void* __restrict__ seed) {
    __shared__ int bad;
    if (threadIdx.x == 0) {
        bad = 0;
        g_minx2bits = 0x7f7fffffu;
        g_ncand = 0;
        g_finaldone = 0;
    }
    if (threadIdx.x < DIM) g_sumx[threadIdx.x] = 0.0;
    __syncthreads();
    unsigned long long v = ((const unsigned long long*)seed)[threadIdx.x];
    if (v >= (unsigned long long)NPTS) atomicOr(&bad, 1);
    __syncthreads();
    if (threadIdx.x == 0) g_seed64 = bad ? 0 : 1;
}

__global__ void x2_kernel(const float* __restrict__ x) {
    __shared__ float wsum[8][DIM];
    const int tid = threadIdx.x;
    const int n = blockIdx.x * 256 + tid;
    const int lane = tid & 31, wid = tid >> 5;
    const bool valid = n < NPTS;
    const float4* r = (const float4*)(x + (size_t)n * DIM);

    float x2 = 0.f;
#pragma unroll
    for (int q = 0; q < 16; q++) {
        float4 v = valid ? r[q] : make_float4(0.f, 0.f, 0.f, 0.f);
        x2 = fmaf(v.x, v.x, x2); x2 = fmaf(v.y, v.y, x2);
        x2 = fmaf(v.z, v.z, x2); x2 = fmaf(v.w, v.w, x2);
#pragma unroll
        for (int off = 16; off > 0; off >>= 1) {
            v.x += __shfl_xor_sync(0xffffffffu, v.x, off);
            v.y += __shfl_xor_sync(0xffffffffu, v.y, off);
            v.z += __shfl_xor_sync(0xffffffffu, v.z, off);
            v.w += __shfl_xor_sync(0xffffffffu, v.w, off);
        }
        if (lane == 0) *(float4*)&wsum[wid][4 * q] = v;
    }
    if (valid) g_x2[n] = x2;
    if (n < NT64) g_tileflag[n] = 0;
    if (n < ITERS) g_chgA[n] = 0;
    {
        float m = valid ? x2 : 1e30f;
#pragma unroll
        for (int off = 16; off > 0; off >>= 1)
            m = fminf(m, __shfl_xor_sync(0xffffffffu, m, off));
        if (lane == 0) atomicMin(&g_minx2bits, __float_as_uint(m));
    }
    __syncthreads();
    if (tid < DIM) {
        float tot = 0.f;
#pragma unroll
        for (int w = 0; w < 8; w++) tot += wsum[w][tid];
        atomicAdd(&g_sumx[tid], (double)tot);
    }
}

__global__ void seed_kernel(const float* __restrict__ x, const void* __restrict__ seedraw) {
    int k = blockIdx.x, d = threadIdx.x;
    long long idx;
    if (g_seed64) idx = ((const long long*)seedraw)[k];
    else          idx = (long long)(((const int*)seedraw)[k]);
    g_c[0][k][d] = x[idx * DIM + d];
    g_acc[k][d] = 0.f;
    if (d == 0) { g_cnt[k] = 0.f; g_best[k] = ~0ull; }
}

__global__ void update_kernel(int it) {
    int k = blockIdx.x, d = threadIdx.x;
    double cnt = (double)NPTS - (double)g_cnt[k];
    double v = (g_sumx[d] - (double)g_acc[k][d]) / cnt;
    __syncthreads();
    g_c[(it + 1) & 1][k][d] = (float)v;
    g_acc[k][d] = 0.f;
    if (d == 0) g_cnt[k] = 0.f;
}

// ------------------------------------------- dense iteration (it=0)
// Round-3 epilogue (direct exception-mask floats, no bit chains, phase 2
// unconditional) + round-10 register prefetch pipeline.

__global__ void __launch_bounds__(256, 1) iter_kernel(const float* __restrict__ x, int it) {
    extern __shared__ float smem[];
    float* Cs  = smem;
    float* c2s = Cs + 64 * KB;
    float* Xt  = c2s + KB;
    float* Xr  = Xt + 64 * XTS;
    float* Ms  = Xr + PB * XRS;
    float* x2s = Ms + PB * MSS;

    const int tid = threadIdx.x;
    const int ty = tid >> 4, tx = tid & 15;
    const int ck0 = ty * 8, p0 = tx * 8, dq = tx * 4;
    const int kb = blockIdx.y * KB;
    const int ploc = tid & 127, d0 = (tid >> 7) * 32;
    const float* cin = &g_c[it & 1][0][0];

    for (int e = tid; e < KB * DIM; e += 256) {
        int ck = e & (KB - 1), d = e >> 7;
        Cs[d * KB + ck] = cin[(size_t)(kb + ck) * DIM + d];
    }
    __syncthreads();
    if (tid < KB) {
        float s = 0.f;
#pragma unroll
        for (int d = 0; d < DIM; d++) { float c = Cs[d * KB + tid]; s = fmaf(c, c, s); }
        c2s[tid] = s;
    }
    __syncthreads();

    u64p c2d[8];
#pragma unroll
    for (int i = 0; i < 8; i++) { float v = c2s[ck0 + i]; PK2(c2d[i], v, v); }
    u64p neg2; { float m2 = -2.0f; PK2(neg2, m2, m2); }

    u64p acc2[4][4];
#pragma unroll
    for (int i = 0; i < 4; i++)
#pragma unroll
        for (int j = 0; j < 4; j++) acc2[i][j] = 0ull;
    float cnt[8] = {0.f, 0.f, 0.f, 0.f, 0.f, 0.f, 0.f, 0.f};

    float4 pf[8];
    float pfx2 = 0.f;
    {
        const int tb = blockIdx.x * PB;
        bool valid = (tb + ploc) < NPTS;
        const float4* src = (const float4*)(x + (size_t)(tb + ploc) * DIM + d0);
#pragma unroll
        for (int k = 0; k < 8; k++)
            pf[k] = valid ? src[k] : make_float4(0.f, 0.f, 0.f, 0.f);
        if (tid < PB) pfx2 = ((tb + tid) < NPTS) ? g_x2[tb + tid] : -1e30f;
    }

    for (int t = blockIdx.x; t < NT128; t += GXI) {
        __syncthreads();
        {
#pragma unroll
            for (int k = 0; k < 8; k++) {
                float4 v = pf[k];
                *(float4*)(Xr + ploc * XRS + d0 + 4 * k) = v;
                Xt[(d0 + 4 * k + 0) * XTS + ploc] = v.x;
                Xt[(d0 + 4 * k + 1) * XTS + ploc] = v.y;
                Xt[(d0 + 4 * k + 2) * XTS + ploc] = v.z;
                Xt[(d0 + 4 * k + 3) * XTS + ploc] = v.w;
            }
            if (tid < PB) x2s[tid] = pfx2;
        }
        __syncthreads();

        const int tn = t + GXI;
        if (tn < NT128) {
            const int tbn = tn * PB;
            bool valid = (tbn + ploc) < NPTS;
            const float4* src = (const float4*)(x + (size_t)(tbn + ploc) * DIM + d0);
#pragma unroll
            for (int k = 0; k < 8; k++)
                pf[k] = valid ? src[k] : make_float4(0.f, 0.f, 0.f, 0.f);
            if (tid < PB) pfx2 = ((tbn + tid) < NPTS) ? g_x2[tbn + tid] : -1e30f;
        }

        // phase 1: dots
        u64p S2[8][4];
#pragma unroll
        for (int i = 0; i < 8; i++)
#pragma unroll
            for (int j = 0; j < 4; j++) S2[i][j] = 0ull;

#pragma unroll 8
        for (int dd = 0; dd < DIM; dd++) {
            float4 ca = *(const float4*)(Cs + dd * KB + ck0);
            float4 cb = *(const float4*)(Cs + dd * KB + ck0 + 4);
            float4 xa = *(const float4*)(Xt + dd * XTS + p0);
            float4 xb = *(const float4*)(Xt + dd * XTS + p0 + 4);
            u64p xp[4];
            PK2(xp[0], xa.x, xa.y); PK2(xp[1], xa.z, xa.w);
            PK2(xp[2], xb.x, xb.y); PK2(xp[3], xb.z, xb.w);
            float cv[8] = {ca.x, ca.y, ca.z, ca.w, cb.x, cb.y, cb.z, cb.w};
#pragma unroll
            for (int i = 0; i < 8; i++) {
                u64p cd; PK2(cd, cv[i], cv[i]);
#pragma unroll
                for (int j = 0; j < 4; j++) FMA2(S2[i][j], cd, xp[j], S2[i][j]);
            }
        }

        // epilogue: exception-mask floats (complement convention) -> Ms
        {
            const int sw = tx & 7;
            const int colA = 4 * ((2 * ty) ^ sw);
            const int colB = 4 * ((2 * ty + 1) ^ sw);
#pragma unroll
            for (int jp = 0; jp < 4; jp++) {
                u64p x2p; PK2(x2p, x2s[p0 + 2 * jp], x2s[p0 + 2 * jp + 1]);
                float mlo[8], mhi[8];
#pragma unroll
                for (int i = 0; i < 8; i++) {
                    u64p tsum; ADD2(tsum, c2d[i], x2p);
                    u64p d2;   FMA2(d2, neg2, S2[i][jp], tsum);
                    float dlo, dhi; UPK2(dlo, dhi, d2);
                    mlo[i] = (dlo < BW2) ? 0.f : 1.f;
                    mhi[i] = (dhi < BW2) ? 0.f : 1.f;
                    cnt[i] += mlo[i] + mhi[i];
                }
                int pA = p0 + 2 * jp, pB = pA + 1;
                *(float4*)(Ms + pA * MSS + colA) = make_float4(mlo[0], mlo[1], mlo[2], mlo[3]);
                *(float4*)(Ms + pA * MSS + colB) = make_float4(mlo[4], mlo[5], mlo[6], mlo[7]);
                *(float4*)(Ms + pB * MSS + colA) = make_float4(mhi[0], mhi[1], mhi[2], mhi[3]);
                *(float4*)(Ms + pB * MSS + colB) = make_float4(mhi[4], mhi[5], mhi[6], mhi[7]);
            }
        }
        __syncthreads();

        // phase 2: acc += M_exc^T X (always; iter0 exceptions are dense)
#pragma unroll 4
        for (int p = 0; p < PB; p++) {
            const int sw2 = (p >> 3) & 7;
            float4 ma = *(const float4*)(Ms + p * MSS + 4 * ((2 * ty) ^ sw2));
            float4 mb = *(const float4*)(Ms + p * MSS + 4 * ((2 * ty + 1) ^ sw2));
            float4 xv = *(const float4*)(Xr + p * XRS + dq);
            u64p mp[4];
            PK2(mp[0], ma.x, ma.y); PK2(mp[1], ma.z, ma.w);
            PK2(mp[2], mb.x, mb.y); PK2(mp[3], mb.z, mb.w);
            u64p xd[4];
            PK2(xd[0], xv.x, xv.x); PK2(xd[1], xv.y, xv.y);
            PK2(xd[2], xv.z, xv.z); PK2(xd[3], xv.w, xv.w);
#pragma unroll
            for (int i2 = 0; i2 < 4; i2++)
#pragma unroll
                for (int j = 0; j < 4; j++) FMA2(acc2[i2][j], mp[i2], xd[j], acc2[i2][j]);
        }
    }

#pragma unroll
    for (int i2 = 0; i2 < 4; i2++)
#pragma unroll
        for (int j = 0; j < 4; j++) {
            float alo, ahi; UPK2(alo, ahi, acc2[i2][j]);
            atomicAdd(&g_acc[kb + ck0 + 2 * i2 + 0][dq + j], alo);
            atomicAdd(&g_acc[kb + ck0 + 2 * i2 + 1][dq + j], ahi);
        }
#pragma unroll
    for (int i = 0; i < 8; i++) {
        float v = cnt[i];
#pragma unroll
        for (int off = 8; off > 0; off >>= 1)
            v += __shfl_down_sync(0xffffffffu, v, off, 16);
        if (tx == 0) atomicAdd(&g_cnt[kb + ck0 + i], v);
    }
}

// ------------------------------------------- persistent sparse iterations 1..9
// + fused sparse final argmin (triangle-pruned candidate set).

static __device__ __forceinline__ void grid_sync() {
    __threadfence();
    __syncthreads();
    if (threadIdx.x == 0) {
        unsigned gen = g_bargen;
        if (atomicAdd(&g_barcnt, 1u) == SPB - 1) {
            g_barcnt = 0;
            __threadfence();
            g_bargen = gen + 1;
        } else {
            while (g_bargen == gen) { __nanosleep(32); }
        }
    }
    __syncthreads();
}

__global__ void __launch_bounds__(256) sparse_all(const float* __restrict__ x) {
    __shared__ float red[KC];
    __shared__ float redB[KC];
    __shared__ unsigned long long rmin[256];
    const int tid = threadIdx.x;
    const int gtid = blockIdx.x * 256 + tid;
    const int stride = SPB * 256;

    // ---- iterations 1..9 with fixed-point early exit ----
    for (int it = 1; it < ITERS; it++) {
        const float* cc = &g_c[it & 1][0][0];
        {
            const float4* cr = (const float4*)(cc + (size_t)tid * DIM);
            float c2 = 0.f;
#pragma unroll
            for (int q = 0; q < 16; q++) {
                float4 v = cr[q];
                c2 = fmaf(v.x, v.x, c2); c2 = fmaf(v.y, v.y, c2);
                c2 = fmaf(v.z, v.z, c2); c2 = fmaf(v.w, v.w, c2);
            }
            red[tid] = c2;
            __syncthreads();
            for (int s = 128; s > 0; s >>= 1) {
                if (tid < s) red[tid] = fmaxf(red[tid], red[tid + s]);
                __syncthreads();
            }
        }
        const float cmax = sqrtf(red[0]) + 1e-3f;
        __syncthreads();
        float tthr = 12.0f - cmax - 1e-3f;
        const float thr2 = (tthr > 0.f) ? tthr * tthr : -1.0f;

        for (int n = gtid; n < NPTS; n += stride) {
            const float x2 = g_x2[n];
            if (x2 < thr2) continue;
            g_tileflag[n >> 6] = 1;

            float xv[DIM];
            const float4* xr = (const float4*)(x + (size_t)n * DIM);
#pragma unroll
            for (int q = 0; q < 16; q++) {
                float4 v = xr[q];
                xv[4 * q + 0] = v.x; xv[4 * q + 1] = v.y;
                xv[4 * q + 2] = v.z; xv[4 * q + 3] = v.w;
            }
            for (int k = 0; k < KC; k++) {
                const float4* cr = (const float4*)(cc + (size_t)k * DIM);
                float dot = 0.f, c2 = 0.f;
#pragma unroll
                for (int q = 0; q < 16; q++) {
                    float4 cv = cr[q];
                    dot = fmaf(cv.x, xv[4 * q + 0], dot);
                    dot = fmaf(cv.y, xv[4 * q + 1], dot);
                    dot = fmaf(cv.z, xv[4 * q + 2], dot);
                    dot = fmaf(cv.w, xv[4 * q + 3], dot);
                    c2 = fmaf(cv.x, cv.x, c2); c2 = fmaf(cv.y, cv.y, c2);
                    c2 = fmaf(cv.z, cv.z, c2); c2 = fmaf(cv.w, cv.w, c2);
                }
                float d2 = c2 + x2 - 2.f * dot;
                if (!(d2 < BW2)) {
                    atomicAdd(&g_cnt[k], 1.0f);
#pragma unroll
                    for (int d = 0; d < DIM; d++) atomicAdd(&g_acc[k][d], xv[d]);
                }
            }
        }

        grid_sync();

        int diff = 0;
        {
            int k = -1, d = tid & 63;
            if (tid < 64) k = blockIdx.x;
            else if (tid < 128) { int kk = blockIdx.x + SPB; if (kk < KC) k = kk; }
            if (k >= 0) {
                double cnt = (double)NPTS - (double)g_cnt[k];
                double v = (g_sumx[d] - (double)g_acc[k][d]) / cnt;
                float nf = (float)v;
                if (__float_as_uint(nf) != __float_as_uint(g_c[it & 1][k][d])) diff = 1;
                g_c[(it + 1) & 1][k][d] = nf;
                g_acc[k][d] = 0.f;
            }
        }
        if (__syncthreads_or(diff) && tid == 0) atomicOr(&g_chgA[it], 1);
        if (tid == 0) {
            g_cnt[blockIdx.x] = 0.f;
            int kk = blockIdx.x + SPB;
            if (kk < KC) g_cnt[kk] = 0.f;
        }

        grid_sync();

        if (g_chgA[it] == 0) break;   // uniform decision across blocks
    }

    // ---- fused sparse final argmin ----
    {
        const float4* ca = (const float4*)&g_c[0][tid][0];
        const float4* cb = (const float4*)&g_c[1][tid][0];
        float c2a = 0.f, c2b = 0.f;
#pragma unroll
        for (int q = 0; q < 16; q++) {
            float4 va = ca[q], vb = cb[q];
            c2a = fmaf(va.x, va.x, c2a); c2a = fmaf(va.y, va.y, c2a);
            c2a = fmaf(va.z, va.z, c2a); c2a = fmaf(va.w, va.w, c2a);
            c2b = fmaf(vb.x, vb.x, c2b); c2b = fmaf(vb.y, vb.y, c2b);
            c2b = fmaf(vb.z, vb.z, c2b); c2b = fmaf(vb.w, vb.w, c2b);
        }
        red[tid] = c2a; redB[tid] = c2b;
        __syncthreads();
        for (int s = 128; s > 0; s >>= 1) {
            if (tid < s) {
                red[tid] = fmaxf(red[tid], red[tid + s]);
                redB[tid] = fmaxf(redB[tid], redB[tid + s]);
            }
            __syncthreads();
        }
    }
    const float cmax10 = sqrtf(red[0]) + 1e-3f;
    const float cmax9  = sqrtf(redB[0]) + 1e-3f;
    const float minx   = sqrtf(__uint_as_float(g_minx2bits));
    const float thr    = minx + 2.f * cmax10 + 0.05f;
    const float thr2   = thr * thr;
    const bool valid   = (minx + cmax9 + 0.05f < 12.0f);

    if (valid) {
        for (int n = gtid; n < NPTS; n += stride) {
            if (g_x2[n] <= thr2) {
                int pos = atomicAdd(&g_ncand, 1);
                if (pos < CCAP) g_cand[pos] = n;
            }
        }
    }
    grid_sync();
    const int ncand = g_ncand;
    if (!valid || ncand == 0 || ncand > CCAP) return;   // dense fallback handles

    for (int k = blockIdx.x; k < KC; k += SPB) {
        unsigned long long bk = ~0ull;
        for (int j = tid; j < ncand; j += 256) {
            const int n = g_cand[j];
            const float* xr = x + (size_t)n * DIM;
            const float x2 = g_x2[n];
            const float* c9r  = &g_c[1][k][0];
            const float* c10r = &g_c[0][k][0];
            float dot9 = 0.f, dot10 = 0.f, c29 = 0.f, c210 = 0.f;
            for (int d = 0; d < DIM; d++) {
                float xv = xr[d], v9 = c9r[d], v10 = c10r[d];
                dot9  = fmaf(v9,  xv, dot9);
                dot10 = fmaf(v10, xv, dot10);
                c29   = fmaf(v9,  v9,  c29);
                c210  = fmaf(v10, v10, c210);
            }
            float d9 = fmaf(-2.f, dot9, c29 + x2);
            if (d9 < BW2) {
                float d2 = fmaxf(fmaf(-2.f, dot10, c210 + x2), 0.f);
                unsigned long long key =
                    ((unsigned long long)__float_as_uint(d2) << 32) | (unsigned)n;
                if (key < bk) bk = key;
            }
        }
        rmin[tid] = bk;
        __syncthreads();
        for (int s = 128; s > 0; s >>= 1) {
            if (tid < s && rmin[tid + s] < rmin[tid]) rmin[tid] = rmin[tid + s];
            __syncthreads();
        }
        if (tid == 0 && rmin[0] != ~0ull) atomicMin(&g_best[k], rmin[0]);
        __syncthreads();
    }
    if (blockIdx.x == 0 && tid == 0) g_finaldone = 1;
}

// ------------------------------------------- dense final (fallback only)

__global__ void __launch_bounds__(256, 2) final_kernel(const float* __restrict__ x) {
    if (g_finaldone) return;
    extern __shared__ float sm[];
    float* Ct   = sm;
    float* c210 = Ct + 64 * KB;
    float* Xt   = c210 + KB;
    float* x2s  = Xt + 64 * XTS;

    const int tid = threadIdx.x;
    const int ty = tid >> 4, tx = tid & 15;
    const int ck0 = ty * 8, p0 = tx * 8;
    const int kb = blockIdx.y * KB;

    for (int e = tid; e < KB * DIM; e += 256) {
        int ck = e & (KB - 1), d = e >> 7;
        Ct[d * KB + ck] = g_c[0][kb + ck][d];
    }
    __syncthreads();
    if (tid < KB) {
        float s = 0.f;
#pragma unroll
        for (int d = 0; d < DIM; d++) { float a = Ct[d * KB + tid]; s = fmaf(a, a, s); }
        c210[tid] = s;
    }
    __syncthreads();

    unsigned long long best[8];
#pragma unroll
    for (int i = 0; i < 8; i++) best[i] = ~0ull;

    for (int t = blockIdx.x; t < NT128; t += GXF) {
        const int tb = t * PB;
        __syncthreads();
        {
            int ploc = tid & 127, d0 = (tid >> 7) * 32;
            bool valid = (tb + ploc) < NPTS;
            const float4* src = (const float4*)(x + (size_t)(tb + ploc) * DIM + d0);
#pragma unroll
            for (int k = 0; k < 8; k++) {
                float4 v = valid ? src[k] : make_float4(0.f, 0.f, 0.f, 0.f);
                Xt[(d0 + 4 * k + 0) * XTS + ploc] = v.x;
                Xt[(d0 + 4 * k + 1) * XTS + ploc] = v.y;
                Xt[(d0 + 4 * k + 2) * XTS + ploc] = v.z;
                Xt[(d0 + 4 * k + 3) * XTS + ploc] = v.w;
            }
            if (tid < PB) x2s[tid] = ((tb + tid) < NPTS) ? g_x2[tb + tid] : 0.f;
        }
        __syncthreads();

        u64p S2[8][4];
#pragma unroll
        for (int i = 0; i < 8; i++)
#pragma unroll
            for (int j = 0; j < 4; j++) S2[i][j] = 0ull;

#pragma unroll 8
        for (int dd = 0; dd < DIM; dd++) {
            float4 ca = *(const float4*)(Ct + dd * KB + ck0);
            float4 cb = *(const float4*)(Ct + dd * KB + ck0 + 4);
            float4 xa = *(const float4*)(Xt + dd * XTS + p0);
            float4 xb = *(const float4*)(Xt + dd * XTS + p0 + 4);
            u64p xp[4];
            PK2(xp[0], xa.x, xa.y); PK2(xp[1], xa.z, xa.w);
            PK2(xp[2], xb.x, xb.y); PK2(xp[3], xb.z, xb.w);
            float cv[8] = {ca.x, ca.y, ca.z, ca.w, cb.x, cb.y, cb.z, cb.w};
#pragma unroll
            for (int i = 0; i < 8; i++) {
                u64p cd; PK2(cd, cv[i], cv[i]);
#pragma unroll
                for (int j = 0; j < 4; j++) FMA2(S2[i][j], cd, xp[j], S2[i][j]);
            }
        }

        const int flagged = g_tileflag[2 * t] |
                            ((2 * t + 1 < NT64) ? g_tileflag[2 * t + 1] : 0);

#pragma unroll
        for (int jp = 0; jp < 4; jp++) {
            const int pA = p0 + 2 * jp, pB = pA + 1;
            const float xa2 = x2s[pA], xb2 = x2s[pB];
            const unsigned ia = (unsigned)(tb + pA), ib = (unsigned)(tb + pB);
#pragma unroll
            for (int i = 0; i < 8; i++) {
                float dlo, dhi; UPK2(dlo, dhi, S2[i][jp]);
                const float c2v = c210[ck0 + i];
                bool oka = true, okb = true;
                if (flagged) {
                    const float* c9r = &g_c[1][kb + ck0 + i][0];
                    float d9a = 0.f, d9b = 0.f, c29v = 0.f;
                    for (int dd = 0; dd < DIM; dd++) {
                        float cv9 = c9r[dd];
                        d9a = fmaf(cv9, Xt[dd * XTS + pA], d9a);
                        d9b = fmaf(cv9, Xt[dd * XTS + pB], d9b);
                        c29v = fmaf(cv9, cv9, c29v);
                    }
                    oka = fmaf(-2.f, d9a, c29v + xa2) < BW2;
                    okb = fmaf(-2.f, d9b, c29v + xb2) < BW2;
                }
                if (oka && ia < NPTS) {
                    float d2 = fmaxf(fmaf(-2.f, dlo, c2v + xa2), 0.f);
                    unsigned long long key =
                        ((unsigned long long)__float_as_uint(d2) << 32) | ia;
                    if (key < best[i]) best[i] = key;
                }
                if (okb && ib < NPTS) {
                    float d2 = fmaxf(fmaf(-2.f, dhi, c2v + xb2), 0.f);
                    unsigned long long key =
                        ((unsigned long long)__float_as_uint(d2) << 32) | ib;
                    if (key < best[i]) best[i] = key;
                }
            }
        }
    }

#pragma unroll
    for (int i = 0; i < 8; i++) {
        unsigned long long v = best[i];
#pragma unroll
        for (int off = 8; off > 0; off >>= 1) {
            unsigned long long o = __shfl_down_sync(0xffffffffu, v, off, 16);
            if (o < v) v = o;
        }
        if (tx == 0) atomicMin(&g_best[kb + ck0 + i], v);
    }
}

// ---------------------------------------------------------------- epilogue

__global__ void zero_out(float* out, int n) {
    int i = blockIdx.x * blockDim.x + threadIdx.x;
    if (i < n) out[i] = 0.f;
}

__global__ void finish_kernel(float* __restrict__ out, const float* __restrict__ x,
                              int out_size) {
    int k = blockIdx.x, d = threadIdx.x;
    if (out_size >= KC * DIM)
        out[k * DIM + d] = g_c[0][k][d];
    unsigned long long b = g_best[k];
    unsigned idx = (b == ~0ull) ? 0u : (unsigned)(b & 0xffffffffu);
    if (out_size >= 2 * KC * DIM)
        out[KC * DIM + k * DIM + d] = x[(size_t)idx * DIM + d];
    if (d == 0 && out_size >= 2 * KC * DIM + KC)
        out[2 * KC * DIM + k] = (float)idx;
}

// ---------------------------------------------------------------- launcher

extern "C" void kernel_launch(void* const* d_in, const int* in_sizes, int n_in,
                              void* d_out, int out_size) {
    const float* x = (const float*)d_in[0];
    const void* seed = d_in[1];
    float* out = (float*)d_out;
    (void)in_sizes; (void)n_in;

    const size_t iterSmem = (size_t)(64 * KB + KB + 64 * XTS + PB * XRS + PB * MSS + PB + 16)
                            * sizeof(float);
    const size_t finalSmem = (size_t)(64 * KB + KB + 64 * XTS + PB) * sizeof(float);
    cudaFuncSetAttribute(iter_kernel,  cudaFuncAttributeMaxDynamicSharedMemorySize, (int)iterSmem);
    cudaFuncSetAttribute(final_kernel, cudaFuncAttributeMaxDynamicSharedMemorySize, (int)finalSmem);

    detect_kernel<<<1, 128>>>(seed);
    x2_kernel<<<(NPTS + 255) / 256, 256>>>(x);
    seed_kernel<<<KC, DIM>>>(x, seed);

    iter_kernel<<<dim3(GXI, KC / KB), 256, iterSmem>>>(x, 0);
    update_kernel<<<KC, DIM>>>(0);

    sparse_all<<<SPB, 256>>>(x);     // iterations 1..9 + sparse final argmin

    final_kernel<<<dim3(GXF, KC / KB), 256, finalSmem>>>(x);   // fallback

    if (out_size > 0)
        zero_out<<<(out_size + 255) / 256, 256>>>(out, out_size);
    finish_kernel<<<KC, DIM>>>(out, x, out_size);
}

// round 14
// speedup vs baseline: 2.8221x; 1.0151x over previous
#include <cuda_runtime.h>
#include <cuda_bf16.h>
#include <stdint.h>

#define NPTS 200000
#define DIM 64
#define KC 256
#define BW2 144.0f
#define ITERS 10

#define KB 128
#define PBI 64           // iter points/tile (64*3125 = 200000 exactly)
#define NTI 3125
#define GXI 148
#define PB 128           // fallback final tile
#define NT128 1563
#define GXF 148
#define XTS 132
#define XTI 68           // iter Xt stride
#define XRS 68
#define MSS 132
#define NT64 3125
#define SPB 148
#define CCAP 4096

typedef unsigned long long u64p;
#define PK2(d, lo, hi) asm("mov.b64 %0, {%1, %2};" : "=l"(d) : "f"(lo), "f"(hi))
#define UPK2(lo, hi, s) asm("mov.b64 {%0, %1}, %2;" : "=f"(lo), "=f"(hi) : "l"(s))
#define FMA2(d, a, b, c) asm("fma.rn.f32x2 %0, %1, %2, %3;" : "=l"(d) : "l"(a), "l"(b), "l"(c))
#define ADD2(d, a, b) asm("add.rn.f32x2 %0, %1, %2;" : "=l"(d) : "l"(a), "l"(b))

__device__ float g_c[2][KC][DIM];
__device__ float g_acc[KC][DIM];
__device__ float g_cnt[KC];
__device__ double g_sumx[DIM];
__device__ float g_x2[NPTS];
__device__ unsigned long long g_best[KC];
__device__ int g_seed64;
__device__ int g_tileflag[NT64];
__device__ int g_chgA[ITERS];
__device__ unsigned g_barcnt;
__device__ volatile unsigned g_bargen;
__device__ unsigned g_minx2bits;
__device__ int g_ncand;
__device__ int g_cand[CCAP];
__device__ int g_finaldone;

// ------------------------------------------------- prologue kernels

__global__ void detect_kernel(const void* __restrict__ seed) {
    __shared__ int bad;
    if (threadIdx.x == 0) {
        bad = 0;
        g_minx2bits = 0x7f7fffffu;
        g_ncand = 0;
        g_finaldone = 0;
    }
    if (threadIdx.x < DIM) g_sumx[threadIdx.x] = 0.0;
    __syncthreads();
    unsigned long long v = ((const unsigned long long*)seed)[threadIdx.x];
    if (v >= (unsigned long long)NPTS) atomicOr(&bad, 1);
    __syncthreads();
    if (threadIdx.x == 0) g_seed64 = bad ? 0 : 1;
}

__global__ void x2_kernel(const float* __restrict__ x) {
    __shared__ float wsum[8][DIM];
    const int tid = threadIdx.x;
    const int n = blockIdx.x * 256 + tid;
    const int lane = tid & 31, wid = tid >> 5;
    const bool valid = n < NPTS;
    const float4* r = (const float4*)(x + (size_t)n * DIM);

    float x2 = 0.f;
#pragma unroll
    for (int q = 0; q < 16; q++) {
        float4 v = valid ? r[q] : make_float4(0.f, 0.f, 0.f, 0.f);
        x2 = fmaf(v.x, v.x, x2); x2 = fmaf(v.y, v.y, x2);
        x2 = fmaf(v.z, v.z, x2); x2 = fmaf(v.w, v.w, x2);
#pragma unroll
        for (int off = 16; off > 0; off >>= 1) {
            v.x += __shfl_xor_sync(0xffffffffu, v.x, off);
            v.y += __shfl_xor_sync(0xffffffffu, v.y, off);
            v.z += __shfl_xor_sync(0xffffffffu, v.z, off);
            v.w += __shfl_xor_sync(0xffffffffu, v.w, off);
        }
        if (lane == 0) *(float4*)&wsum[wid][4 * q] = v;
    }
    if (valid) g_x2[n] = x2;
    if (n < NT64) g_tileflag[n] = 0;
    if (n < ITERS) g_chgA[n] = 0;
    {
        float m = valid ? x2 : 1e30f;
#pragma unroll
        for (int off = 16; off > 0; off >>= 1)
            m = fminf(m, __shfl_xor_sync(0xffffffffu, m, off));
        if (lane == 0) atomicMin(&g_minx2bits, __float_as_uint(m));
    }
    __syncthreads();
    if (tid < DIM) {
        float tot = 0.f;
#pragma unroll
        for (int w = 0; w < 8; w++) tot += wsum[w][tid];
        atomicAdd(&g_sumx[tid], (double)tot);
    }
}

__global__ void seed_kernel(const float* __restrict__ x, const void* __restrict__ seedraw) {
    int k = blockIdx.x, d = threadIdx.x;
    long long idx;
    if (g_seed64) idx = ((const long long*)seedraw)[k];
    else          idx = (long long)(((const int*)seedraw)[k]);
    g_c[0][k][d] = x[idx * DIM + d];
    g_acc[k][d] = 0.f;
    if (d == 0) { g_cnt[k] = 0.f; g_best[k] = ~0ull; }
}

__global__ void update_kernel(int it) {
    int k = blockIdx.x, d = threadIdx.x;
    double cnt = (double)NPTS - (double)g_cnt[k];
    double v = (g_sumx[d] - (double)g_acc[k][d]) / cnt;
    __syncthreads();
    g_c[(it + 1) & 1][k][d] = (float)v;
    g_acc[k][d] = 0.f;
    if (d == 0) g_cnt[k] = 0.f;
}

// ------------------------------------------- dense iteration (it=0)
// 128 centers x 64 points per tile, 102KB smem -> 2 CTAs/SM, prefetch pipeline.

__global__ void __launch_bounds__(256, 2) iter_kernel(const float* __restrict__ x, int it) {
    extern __shared__ float smem[];
    float* Cs  = smem;                // [64][128]
    float* c2s = Cs + 64 * KB;        // [128]
    float* Xt  = c2s + KB;            // [64][68]
    float* Xr  = Xt + 64 * XTI;       // [64][68]
    float* Ms  = Xr + PBI * XRS;      // [64][132]
    float* x2s = Ms + PBI * MSS;      // [64]

    const int tid = threadIdx.x;
    const int ty = tid >> 4, tx = tid & 15;
    const int ck0 = ty * 8, p0 = tx * 4, dq = tx * 4;
    const int kb = blockIdx.y * KB;
    const int ploc = tid & 63, d0 = (tid >> 6) * 16;
    const float* cin = &g_c[it & 1][0][0];

    for (int e = tid; e < KB * DIM; e += 256) {
        int ck = e & (KB - 1), d = e >> 7;
        Cs[d * KB + ck] = cin[(size_t)(kb + ck) * DIM + d];
    }
    __syncthreads();
    if (tid < KB) {
        float s = 0.f;
#pragma unroll
        for (int d = 0; d < DIM; d++) { float c = Cs[d * KB + tid]; s = fmaf(c, c, s); }
        c2s[tid] = s;
    }
    __syncthreads();

    float c2f[8];
#pragma unroll
    for (int i = 0; i < 8; i++) c2f[i] = c2s[ck0 + i];
    u64p neg2; { float m2 = -2.0f; PK2(neg2, m2, m2); }

    u64p acc2[4][4];
#pragma unroll
    for (int i = 0; i < 4; i++)
#pragma unroll
        for (int j = 0; j < 4; j++) acc2[i][j] = 0ull;
    float cnt[8] = {0.f, 0.f, 0.f, 0.f, 0.f, 0.f, 0.f, 0.f};

    // prefetch first tile (no bounds checks: 64 | 200000)
    float4 pf[4];
    float pfx2 = 0.f;
    {
        const int tb = blockIdx.x * PBI;
        const float4* src = (const float4*)(x + (size_t)(tb + ploc) * DIM + d0);
#pragma unroll
        for (int k = 0; k < 4; k++) pf[k] = src[k];
        if (tid < PBI) pfx2 = g_x2[tb + tid];
    }

    for (int t = blockIdx.x; t < NTI; t += GXI) {
        __syncthreads();
        {
#pragma unroll
            for (int k = 0; k < 4; k++) {
                float4 v = pf[k];
                *(float4*)(Xr + ploc * XRS + d0 + 4 * k) = v;
                Xt[(d0 + 4 * k + 0) * XTI + ploc] = v.x;
                Xt[(d0 + 4 * k + 1) * XTI + ploc] = v.y;
                Xt[(d0 + 4 * k + 2) * XTI + ploc] = v.z;
                Xt[(d0 + 4 * k + 3) * XTI + ploc] = v.w;
            }
            if (tid < PBI) x2s[tid] = pfx2;
        }
        __syncthreads();

        const int tn = t + GXI;
        if (tn < NTI) {
            const int tbn = tn * PBI;
            const float4* src = (const float4*)(x + (size_t)(tbn + ploc) * DIM + d0);
#pragma unroll
            for (int k = 0; k < 4; k++) pf[k] = src[k];
            if (tid < PBI) pfx2 = g_x2[tbn + tid];
        }

        // phase 1: dots (8 centers x 4 points -> 8x2 pairs)
        u64p S2[8][2];
#pragma unroll
        for (int i = 0; i < 8; i++) { S2[i][0] = 0ull; S2[i][1] = 0ull; }

#pragma unroll 8
        for (int dd = 0; dd < DIM; dd++) {
            float4 ca = *(const float4*)(Cs + dd * KB + ck0);
            float4 cb = *(const float4*)(Cs + dd * KB + ck0 + 4);
            float4 xa = *(const float4*)(Xt + dd * XTI + p0);
            u64p xp[2];
            PK2(xp[0], xa.x, xa.y); PK2(xp[1], xa.z, xa.w);
            float cv[8] = {ca.x, ca.y, ca.z, ca.w, cb.x, cb.y, cb.z, cb.w};
#pragma unroll
            for (int i = 0; i < 8; i++) {
                u64p cd; PK2(cd, cv[i], cv[i]);
                FMA2(S2[i][0], cd, xp[0], S2[i][0]);
                FMA2(S2[i][1], cd, xp[1], S2[i][1]);
            }
        }

        // epilogue: exception-mask floats -> Ms (swizzle key = (p>>2)&7 = tx&7)
        {
            const int sw = tx & 7;
            const int colA = 4 * ((2 * ty) ^ sw);
            const int colB = 4 * ((2 * ty + 1) ^ sw);
#pragma unroll
            for (int jp = 0; jp < 2; jp++) {
                u64p x2p; PK2(x2p, x2s[p0 + 2 * jp], x2s[p0 + 2 * jp + 1]);
                float mlo[8], mhi[8];
#pragma unroll
                for (int i = 0; i < 8; i++) {
                    u64p c2d; PK2(c2d, c2f[i], c2f[i]);
                    u64p tsum; ADD2(tsum, c2d, x2p);
                    u64p d2;   FMA2(d2, neg2, S2[i][jp], tsum);
                    float dlo, dhi; UPK2(dlo, dhi, d2);
                    mlo[i] = (dlo < BW2) ? 0.f : 1.f;
                    mhi[i] = (dhi < BW2) ? 0.f : 1.f;
                    cnt[i] += mlo[i] + mhi[i];
                }
                int pA = p0 + 2 * jp, pB = pA + 1;
                *(float4*)(Ms + pA * MSS + colA) = make_float4(mlo[0], mlo[1], mlo[2], mlo[3]);
                *(float4*)(Ms + pA * MSS + colB) = make_float4(mlo[4], mlo[5], mlo[6], mlo[7]);
                *(float4*)(Ms + pB * MSS + colA) = make_float4(mhi[0], mhi[1], mhi[2], mhi[3]);
                *(float4*)(Ms + pB * MSS + colB) = make_float4(mhi[4], mhi[5], mhi[6], mhi[7]);
            }
        }
        __syncthreads();

        // phase 2: acc += M_exc^T X
#pragma unroll 4
        for (int p = 0; p < PBI; p++) {
            const int sw2 = (p >> 2) & 7;
            float4 ma = *(const float4*)(Ms + p * MSS + 4 * ((2 * ty) ^ sw2));
            float4 mb = *(const float4*)(Ms + p * MSS + 4 * ((2 * ty + 1) ^ sw2));
            float4 xv = *(const float4*)(Xr + p * XRS + dq);
            u64p mp[4];
            PK2(mp[0], ma.x, ma.y); PK2(mp[1], ma.z, ma.w);
            PK2(mp[2], mb.x, mb.y); PK2(mp[3], mb.z, mb.w);
            u64p xd[4];
            PK2(xd[0], xv.x, xv.x); PK2(xd[1], xv.y, xv.y);
            PK2(xd[2], xv.z, xv.z); PK2(xd[3], xv.w, xv.w);
#pragma unroll
            for (int i2 = 0; i2 < 4; i2++)
#pragma unroll
                for (int j = 0; j < 4; j++) FMA2(acc2[i2][j], mp[i2], xd[j], acc2[i2][j]);
        }
    }

#pragma unroll
    for (int i2 = 0; i2 < 4; i2++)
#pragma unroll
        for (int j = 0; j < 4; j++) {
            float alo, ahi; UPK2(alo, ahi, acc2[i2][j]);
            atomicAdd(&g_acc[kb + ck0 + 2 * i2 + 0][dq + j], alo);
            atomicAdd(&g_acc[kb + ck0 + 2 * i2 + 1][dq + j], ahi);
        }
#pragma unroll
    for (int i = 0; i < 8; i++) {
        float v = cnt[i];
#pragma unroll
        for (int off = 8; off > 0; off >>= 1)
            v += __shfl_down_sync(0xffffffffu, v, off, 16);
        if (tx == 0) atomicAdd(&g_cnt[kb + ck0 + i], v);
    }
}

// ------------------------------------------- persistent sparse iterations 1..9
// + fused sparse final argmin.

static __device__ __forceinline__ void grid_sync() {
    __threadfence();
    __syncthreads();
    if (threadIdx.x == 0) {
        unsigned gen = g_bargen;
        if (atomicAdd(&g_barcnt, 1u) == SPB - 1) {
            g_barcnt = 0;
            __threadfence();
            g_bargen = gen + 1;
        } else {
            while (g_bargen == gen) { __nanosleep(32); }
        }
    }
    __syncthreads();
}

__global__ void __launch_bounds__(256) sparse_all(const float* __restrict__ x) {
    __shared__ float red[KC];
    __shared__ float redB[KC];
    __shared__ unsigned long long rmin[256];
    const int tid = threadIdx.x;
    const int gtid = blockIdx.x * 256 + tid;
    const int stride = SPB * 256;

    for (int it = 1; it < ITERS; it++) {
        const float* cc = &g_c[it & 1][0][0];
        {
            const float4* cr = (const float4*)(cc + (size_t)tid * DIM);
            float c2 = 0.f;
#pragma unroll
            for (int q = 0; q < 16; q++) {
                float4 v = cr[q];
                c2 = fmaf(v.x, v.x, c2); c2 = fmaf(v.y, v.y, c2);
                c2 = fmaf(v.z, v.z, c2); c2 = fmaf(v.w, v.w, c2);
            }
            red[tid] = c2;
            __syncthreads();
            for (int s = 128; s > 0; s >>= 1) {
                if (tid < s) red[tid] = fmaxf(red[tid], red[tid + s]);
                __syncthreads();
            }
        }
        const float cmax = sqrtf(red[0]) + 1e-3f;
        __syncthreads();
        float tthr = 12.0f - cmax - 1e-3f;
        const float thr2 = (tthr > 0.f) ? tthr * tthr : -1.0f;

        for (int n = gtid; n < NPTS; n += stride) {
            const float x2 = g_x2[n];
            if (x2 < thr2) continue;
            g_tileflag[n >> 6] = 1;

            float xv[DIM];
            const float4* xr = (const float4*)(x + (size_t)n * DIM);
#pragma unroll
            for (int q = 0; q < 16; q++) {
                float4 v = xr[q];
                xv[4 * q + 0] = v.x; xv[4 * q + 1] = v.y;
                xv[4 * q + 2] = v.z; xv[4 * q + 3] = v.w;
            }
            for (int k = 0; k < KC; k++) {
                const float4* cr = (const float4*)(cc + (size_t)k * DIM);
                float dot = 0.f, c2 = 0.f;
#pragma unroll
                for (int q = 0; q < 16; q++) {
                    float4 cv = cr[q];
                    dot = fmaf(cv.x, xv[4 * q + 0], dot);
                    dot = fmaf(cv.y, xv[4 * q + 1], dot);
                    dot = fmaf(cv.z, xv[4 * q + 2], dot);
                    dot = fmaf(cv.w, xv[4 * q + 3], dot);
                    c2 = fmaf(cv.x, cv.x, c2); c2 = fmaf(cv.y, cv.y, c2);
                    c2 = fmaf(cv.z, cv.z, c2); c2 = fmaf(cv.w, cv.w, c2);
                }
                float d2 = c2 + x2 - 2.f * dot;
                if (!(d2 < BW2)) {
                    atomicAdd(&g_cnt[k], 1.0f);
#pragma unroll
                    for (int d = 0; d < DIM; d++) atomicAdd(&g_acc[k][d], xv[d]);
                }
            }
        }

        grid_sync();

        int diff = 0;
        {
            int k = -1, d = tid & 63;
            if (tid < 64) k = blockIdx.x;
            else if (tid < 128) { int kk = blockIdx.x + SPB; if (kk < KC) k = kk; }
            if (k >= 0) {
                double cnt = (double)NPTS - (double)g_cnt[k];
                double v = (g_sumx[d] - (double)g_acc[k][d]) / cnt;
                float nf = (float)v;
                if (__float_as_uint(nf) != __float_as_uint(g_c[it & 1][k][d])) diff = 1;
                g_c[(it + 1) & 1][k][d] = nf;
                g_acc[k][d] = 0.f;
            }
        }
        if (__syncthreads_or(diff) && tid == 0) atomicOr(&g_chgA[it], 1);
        if (tid == 0) {
            g_cnt[blockIdx.x] = 0.f;
            int kk = blockIdx.x + SPB;
            if (kk < KC) g_cnt[kk] = 0.f;
        }

        grid_sync();

        if (g_chgA[it] == 0) break;
    }

    // ---- fused sparse final argmin ----
    {
        const float4* ca = (const float4*)&g_c[0][tid][0];
        const float4* cb = (const float4*)&g_c[1][tid][0];
        float c2a = 0.f, c2b = 0.f;
#pragma unroll
        for (int q = 0; q < 16; q++) {
            float4 va = ca[q], vb = cb[q];
            c2a = fmaf(va.x, va.x, c2a); c2a = fmaf(va.y, va.y, c2a);
            c2a = fmaf(va.z, va.z, c2a); c2a = fmaf(va.w, va.w, c2a);
            c2b = fmaf(vb.x, vb.x, c2b); c2b = fmaf(vb.y, vb.y, c2b);
            c2b = fmaf(vb.z, vb.z, c2b); c2b = fmaf(vb.w, vb.w, c2b);
        }
        red[tid] = c2a; redB[tid] = c2b;
        __syncthreads();
        for (int s = 128; s > 0; s >>= 1) {
            if (tid < s) {
                red[tid] = fmaxf(red[tid], red[tid + s]);
                redB[tid] = fmaxf(redB[tid], redB[tid + s]);
            }
            __syncthreads();
        }
    }
    const float cmax10 = sqrtf(red[0]) + 1e-3f;
    const float cmax9  = sqrtf(redB[0]) + 1e-3f;
    const float minx   = sqrtf(__uint_as_float(g_minx2bits));
    const float thr    = minx + 2.f * cmax10 + 0.05f;
    const float thr2   = thr * thr;
    const bool valid   = (minx + cmax9 + 0.05f < 12.0f);

    if (valid) {
        for (int n = gtid; n < NPTS; n += stride) {
            if (g_x2[n] <= thr2) {
                int pos = atomicAdd(&g_ncand, 1);
                if (pos < CCAP) g_cand[pos] = n;
            }
        }
    }
    grid_sync();
    const int ncand = g_ncand;
    if (!valid || ncand == 0 || ncand > CCAP) return;

    for (int k = blockIdx.x; k < KC; k += SPB) {
        unsigned long long bk = ~0ull;
        for (int j = tid; j < ncand; j += 256) {
            const int n = g_cand[j];
            const float* xr = x + (size_t)n * DIM;
            const float x2 = g_x2[n];
            const float* c9r  = &g_c[1][k][0];
            const float* c10r = &g_c[0][k][0];
            float dot9 = 0.f, dot10 = 0.f, c29 = 0.f, c210 = 0.f;
            for (int d = 0; d < DIM; d++) {
                float xv = xr[d], v9 = c9r[d], v10 = c10r[d];
                dot9  = fmaf(v9,  xv, dot9);
                dot10 = fmaf(v10, xv, dot10);
                c29   = fmaf(v9,  v9,  c29);
                c210  = fmaf(v10, v10, c210);
            }
            float d9 = fmaf(-2.f, dot9, c29 + x2);
            if (d9 < BW2) {
                float d2 = fmaxf(fmaf(-2.f, dot10, c210 + x2), 0.f);
                unsigned long long key =
                    ((unsigned long long)__float_as_uint(d2) << 32) | (unsigned)n;
                if (key < bk) bk = key;
            }
        }
        rmin[tid] = bk;
        __syncthreads();
        for (int s = 128; s > 0; s >>= 1) {
            if (tid < s && rmin[tid + s] < rmin[tid]) rmin[tid] = rmin[tid + s];
            __syncthreads();
        }
        if (tid == 0 && rmin[0] != ~0ull) atomicMin(&g_best[k], rmin[0]);
        __syncthreads();
    }
    if (blockIdx.x == 0 && tid == 0) g_finaldone = 1;
}

// ------------------------------------------- dense final (fallback only)

__global__ void __launch_bounds__(256, 2) final_kernel(const float* __restrict__ x) {
    if (g_finaldone) return;
    extern __shared__ float sm[];
    float* Ct   = sm;
    float* c210 = Ct + 64 * KB;
    float* Xt   = c210 + KB;
    float* x2s  = Xt + 64 * XTS;

    const int tid = threadIdx.x;
    const int ty = tid >> 4, tx = tid & 15;
    const int ck0 = ty * 8, p0 = tx * 8;
    const int kb = blockIdx.y * KB;

    for (int e = tid; e < KB * DIM; e += 256) {
        int ck = e & (KB - 1), d = e >> 7;
        Ct[d * KB + ck] = g_c[0][kb + ck][d];
    }
    __syncthreads();
    if (tid < KB) {
        float s = 0.f;
#pragma unroll
        for (int d = 0; d < DIM; d++) { float a = Ct[d * KB + tid]; s = fmaf(a, a, s); }
        c210[tid] = s;
    }
    __syncthreads();

    unsigned long long best[8];
#pragma unroll
    for (int i = 0; i < 8; i++) best[i] = ~0ull;

    for (int t = blockIdx.x; t < NT128; t += GXF) {
        const int tb = t * PB;
        __syncthreads();
        {
            int ploc = tid & 127, d0 = (tid >> 7) * 32;
            bool valid = (tb + ploc) < NPTS;
            const float4* src = (const float4*)(x + (size_t)(tb + ploc) * DIM + d0);
#pragma unroll
            for (int k = 0; k < 8; k++) {
                float4 v = valid ? src[k] : make_float4(0.f, 0.f, 0.f, 0.f);
                Xt[(d0 + 4 * k + 0) * XTS + ploc] = v.x;
                Xt[(d0 + 4 * k + 1) * XTS + ploc] = v.y;
                Xt[(d0 + 4 * k + 2) * XTS + ploc] = v.z;
                Xt[(d0 + 4 * k + 3) * XTS + ploc] = v.w;
            }
            if (tid < PB) x2s[tid] = ((tb + tid) < NPTS) ? g_x2[tb + tid] : 0.f;
        }
        __syncthreads();

        u64p S2[8][4];
#pragma unroll
        for (int i = 0; i < 8; i++)
#pragma unroll
            for (int j = 0; j < 4; j++) S2[i][j] = 0ull;

#pragma unroll 8
        for (int dd = 0; dd < DIM; dd++) {
            float4 ca = *(const float4*)(Ct + dd * KB + ck0);
            float4 cb = *(const float4*)(Ct + dd * KB + ck0 + 4);
            float4 xa = *(const float4*)(Xt + dd * XTS + p0);
            float4 xb = *(const float4*)(Xt + dd * XTS + p0 + 4);
            u64p xp[4];
            PK2(xp[0], xa.x, xa.y); PK2(xp[1], xa.z, xa.w);
            PK2(xp[2], xb.x, xb.y); PK2(xp[3], xb.z, xb.w);
            float cv[8] = {ca.x, ca.y, ca.z, ca.w, cb.x, cb.y, cb.z, cb.w};
#pragma unroll
            for (int i = 0; i < 8; i++) {
                u64p cd; PK2(cd, cv[i], cv[i]);
#pragma unroll
                for (int j = 0; j < 4; j++) FMA2(S2[i][j], cd, xp[j], S2[i][j]);
            }
        }

        const int flagged = g_tileflag[2 * t] |
                            ((2 * t + 1 < NT64) ? g_tileflag[2 * t + 1] : 0);

#pragma unroll
        for (int jp = 0; jp < 4; jp++) {
            const int pA = p0 + 2 * jp, pB = pA + 1;
            const float xa2 = x2s[pA], xb2 = x2s[pB];
            const unsigned ia = (unsigned)(tb + pA), ib = (unsigned)(tb + pB);
#pragma unroll
            for (int i = 0; i < 8; i++) {
                float dlo, dhi; UPK2(dlo, dhi, S2[i][jp]);
                const float c2v = c210[ck0 + i];
                bool oka = true, okb = true;
                if (flagged) {
                    const float* c9r = &g_c[1][kb + ck0 + i][0];
                    float d9a = 0.f, d9b = 0.f, c29v = 0.f;
                    for (int dd = 0; dd < DIM; dd++) {
                        float cv9 = c9r[dd];
                        d9a = fmaf(cv9, Xt[dd * XTS + pA], d9a);
                        d9b = fmaf(cv9, Xt[dd * XTS + pB], d9b);
                        c29v = fmaf(cv9, cv9, c29v);
                    }
                    oka = fmaf(-2.f, d9a, c29v + xa2) < BW2;
                    okb = fmaf(-2.f, d9b, c29v + xb2) < BW2;
                }
                if (oka && ia < NPTS) {
                    float d2 = fmaxf(fmaf(-2.f, dlo, c2v + xa2), 0.f);
                    unsigned long long key =
                        ((unsigned long long)__float_as_uint(d2) << 32) | ia;
                    if (key < best[i]) best[i] = key;
                }
                if (okb && ib < NPTS) {
                    float d2 = fmaxf(fmaf(-2.f, dhi, c2v + xb2), 0.f);
                    unsigned long long key =
                        ((unsigned long long)__float_as_uint(d2) << 32) | ib;
                    if (key < best[i]) best[i] = key;
                }
            }
        }
    }

#pragma unroll
    for (int i = 0; i < 8; i++) {
        unsigned long long v = best[i];
#pragma unroll
        for (int off = 8; off > 0; off >>= 1) {
            unsigned long long o = __shfl_down_sync(0xffffffffu, v, off, 16);
            if (o < v) v = o;
        }
        if (tx == 0) atomicMin(&g_best[kb + ck0 + i], v);
    }
}

// ---------------------------------------------------------------- epilogue

__global__ void zero_out(float* out, int n) {
    int i = blockIdx.x * blockDim.x + threadIdx.x;
    if (i < n) out[i] = 0.f;
}

__global__ void finish_kernel(float* __restrict__ out, const float* __restrict__ x,
                              int out_size) {
    int k = blockIdx.x, d = threadIdx.x;
    if (out_size >= KC * DIM)
        out[k * DIM + d] = g_c[0][k][d];
    unsigned long long b = g_best[k];
    unsigned idx = (b == ~0ull) ? 0u : (unsigned)(b & 0xffffffffu);
    if (out_size >= 2 * KC * DIM)
        out[KC * DIM + k * DIM + d] = x[(size_t)idx * DIM + d];
    if (d == 0 && out_size >= 2 * KC * DIM + KC)
        out[2 * KC * DIM + k] = (float)idx;
}

// ---------------------------------------------------------------- launcher

extern "C" void kernel_launch(void* const* d_in, const int* in_sizes, int n_in,
                              void* d_out, int out_size) {
    const float* x = (const float*)d_in[0];
    const void* seed = d_in[1];
    float* out = (float*)d_out;
    (void)in_sizes; (void)n_in;

    const size_t iterSmem = (size_t)(64 * KB + KB + 64 * XTI + PBI * XRS + PBI * MSS + PBI)
                            * sizeof(float);
    const size_t finalSmem = (size_t)(64 * KB + KB + 64 * XTS + PB) * sizeof(float);
    cudaFuncSetAttribute(iter_kernel,  cudaFuncAttributeMaxDynamicSharedMemorySize, (int)iterSmem);
    cudaFuncSetAttribute(final_kernel, cudaFuncAttributeMaxDynamicSharedMemorySize, (int)finalSmem);

    detect_kernel<<<1, 128>>>(seed);
    x2_kernel<<<(NPTS + 255) / 256, 256>>>(x);
    seed_kernel<<<KC, DIM>>>(x, seed);

    iter_kernel<<<dim3(GXI, KC / KB), 256, iterSmem>>>(x, 0);
    update_kernel<<<KC, DIM>>>(0);

    sparse_all<<<SPB, 256>>>(x);     // iterations 1..9 + sparse final argmin

    final_kernel<<<dim3(GXF, KC / KB), 256, finalSmem>>>(x);   // fallback

    if (out_size > 0)
        zero_out<<<(out_size + 255) / 256, 256>>>(out, out_size);
    finish_kernel<<<KC, DIM>>>(out, x, out_size);
}